// round 13
// baseline (speedup 1.0000x reference)
#include <cuda_runtime.h>
#include <cuda_fp16.h>
#include <math.h>
#include <stdint.h>

// Problem dims
#define NTOK 32768
#define ADIM 6
#define HDIM 1024
#define DDIM 128
#define KCB  4096

// Output layout (float32, concatenated in reference-return order)
#define OUT_INDS 0
#define OUT_Q    (NTOK)
#define OUT_REC  (NTOK + NTOK * DDIM)
#define OUT_LOSS (NTOK + NTOK * DDIM + NTOK * ADIM)

#define CAPS 64
#define TAU 8e-6f
#define VQ2_BLOCKS (NTOK / 8)   // 4096

// -------- scratch (device globals; no runtime allocation) --------
__device__ float g_h1[NTOK * HDIM];
__device__ __half g_h1h[NTOK * HDIM];  // fp16 h1 (decoder intermediate)
__device__ float g_h2[NTOK * HDIM];
__device__ float g_lat[NTOK * DDIM];
__device__ __half g_qh[NTOK * DDIM];   // fp16 quantized_st (decoder input)
__device__ float g_ln[NTOK];
__device__ float g_cn[KCB];
__device__ __half g_cbh[KCB * DDIM];   // fp16 codebook (screen only)
__device__ float g_part[VQ2_BLOCKS];
__device__ __half g_wt1[HDIM * DDIM];  // Wd1^T fp16
__device__ __half g_wt2[HDIM * HDIM];  // Wd2^T fp16
__device__ unsigned short g_cand[NTOK * CAPS];
__device__ int g_ccnt[NTOK];

__device__ __forceinline__ uint32_t smem_u32(const void* p)
{
    uint32_t a;
    asm("{ .reg .u64 t; cvta.to.shared.u64 t, %1; cvt.u32.u64 %0, t; }"
        : "=r"(a) : "l"(p));
    return a;
}
__device__ __forceinline__ void cp16(uint32_t dst, const void* src)
{
    asm volatile("cp.async.cg.shared.global [%0], [%1], 16;"
                 :: "r"(dst), "l"(src) : "memory");
}
__device__ __forceinline__ void mma_f16(float* c, const uint32_t* a, const uint32_t* b)
{
    asm("mma.sync.aligned.m16n8k16.row.col.f32.f16.f16.f32 "
        "{%0,%1,%2,%3}, {%4,%5,%6,%7}, {%8,%9}, {%0,%1,%2,%3};"
        : "+f"(c[0]), "+f"(c[1]), "+f"(c[2]), "+f"(c[3])
        : "r"(a[0]), "r"(a[1]), "r"(a[2]), "r"(a[3]), "r"(b[0]), "r"(b[1]));
}

// ---------------------------------------------------------------------------
// Codebook norms + fp16 codebook (XLA-order reduction, argmin-tie critical)
// ---------------------------------------------------------------------------
__global__ void k_cnorm(const float* __restrict__ cb, float* __restrict__ cn,
                        __half* __restrict__ cbh)
{
    int w = (blockIdx.x * blockDim.x + threadIdx.x) >> 5;
    int lane = threadIdx.x & 31;
    const float* row = cb + w * DDIM;
    __half* hrow = cbh + (size_t)w * DDIM;
    float acc = 0.f;
#pragma unroll
    for (int i = 0; i < 4; i++) {
        float v = row[lane + i * 32];
        hrow[lane + i * 32] = __float2half_rn(v);
        acc = __fadd_rn(acc, __fmul_rn(v, v));
    }
#pragma unroll
    for (int off = 16; off >= 1; off >>= 1)
        acc = __fadd_rn(acc, __shfl_down_sync(0xffffffffu, acc, off));
    if (lane == 0) cn[w] = acc;
}

__global__ void k_rownorm(const float* __restrict__ lat, float* __restrict__ ln)
{
    int w = (blockIdx.x * blockDim.x + threadIdx.x) >> 5;
    int lane = threadIdx.x & 31;
    const float* row = lat + w * DDIM;
    float acc = 0.f;
#pragma unroll
    for (int i = 0; i < 4; i++) {
        float v = row[lane + i * 32];
        acc = __fadd_rn(acc, __fmul_rn(v, v));
    }
#pragma unroll
    for (int off = 16; off >= 1; off >>= 1)
        acc = __fadd_rn(acc, __shfl_down_sync(0xffffffffu, acc, off));
    if (lane == 0) ln[w] = acc;
}

// ---------------------------------------------------------------------------
// Encoder layer 1 (A=6), 4 outputs/thread (round-11 proven)
// ---------------------------------------------------------------------------
__global__ void k_enc1(const float* __restrict__ act, const float* __restrict__ W1,
                       const float* __restrict__ b1, float* __restrict__ h1)
{
    int gid = blockIdx.x * blockDim.x + threadIdx.x;
    int n = gid >> 8;
    int h = (gid & 255) * 4;
    const float* a = act + n * ADIM;
    float av[ADIM];
#pragma unroll
    for (int k = 0; k < ADIM; k++) av[k] = a[k];
    float4 s = make_float4(0.f, 0.f, 0.f, 0.f);
#pragma unroll
    for (int k = 0; k < ADIM; k++) {
        float4 w = *(const float4*)(W1 + k * HDIM + h);
        s.x = __fmaf_rn(av[k], w.x, s.x);
        s.y = __fmaf_rn(av[k], w.y, s.y);
        s.z = __fmaf_rn(av[k], w.z, s.z);
        s.w = __fmaf_rn(av[k], w.w, s.w);
    }
    float4 b = *(const float4*)(b1 + h);
    s.x = fmaxf(__fadd_rn(s.x, b.x), 0.f);
    s.y = fmaxf(__fadd_rn(s.y, b.y), 0.f);
    s.z = fmaxf(__fadd_rn(s.z, b.z), 0.f);
    s.w = fmaxf(__fadd_rn(s.w, b.w), 0.f);
    *(float4*)(h1 + (size_t)n * HDIM + h) = s;
}

// ---------------------------------------------------------------------------
// FP32 SGEMM v2: cp.async 3-stage pipeline, per-output accumulation chain
// byte-identical to the round-3 proven kernel (single acc, k ascending FFMA).
// A staged as [c(16B chunk)][row][4] so cp.async chunks are contiguous.
// ENCODER ONLY (argmin-critical path).
// ---------------------------------------------------------------------------
#define SGP_STAGE 2048                 // floats per stage: A 1024 + B 1024
template <int RELU>
__global__ __launch_bounds__(256, 2)
void sgemm(const float* __restrict__ Am, const float* __restrict__ Bm,
           const float* __restrict__ bias, float* __restrict__ Cm,
           int M, int Nn, int Kk)
{
    __shared__ float sp[3 * SGP_STAGE];          // 24KB
    uint32_t sb = smem_u32(sp);

    int tid = threadIdx.x;
    int tx = tid & 15;
    int ty = tid >> 4;
    int mb = blockIdx.y * 128;
    int nb = blockIdx.x * 128;

    int arow = tid >> 1;            // 0..127
    int ac = tid & 1;               // 16B chunk within the 8-k stage
    int brow = tid >> 5;            // 0..7
    int bcol = (tid & 31) * 4;

    const float* Ap = Am + (size_t)(mb + arow) * Kk + ac * 4;
    const float* Bp = Bm + (size_t)brow * Nn + nb + bcol;
    uint32_t a_off = (uint32_t)(ac * 512 + arow * 4) * 4;          // bytes
    uint32_t b_off = (uint32_t)(1024 + brow * 128 + bcol) * 4;

    float acc[8][8];
#pragma unroll
    for (int i = 0; i < 8; i++)
#pragma unroll
        for (int j = 0; j < 8; j++) acc[i][j] = 0.f;

    int NS = Kk >> 3;

    // prologue: stages 0,1 in flight
#pragma unroll
    for (int p = 0; p < 2; p++) {
        uint32_t base = sb + (uint32_t)(p * SGP_STAGE) * 4;
        cp16(base + a_off, Ap + p * 8);
        cp16(base + b_off, Bp + (size_t)(p * 8) * Nn);
        asm volatile("cp.async.commit_group;" ::: "memory");
    }

    for (int s = 0; s < NS; s++) {
        asm volatile("cp.async.wait_group 1;" ::: "memory");
        __syncthreads();

        int p2 = s + 2;
        if (p2 < NS) {
            int nbuf = p2 - (p2 / 3) * 3;
            uint32_t base = sb + (uint32_t)(nbuf * SGP_STAGE) * 4;
            cp16(base + a_off, Ap + p2 * 8);
            cp16(base + b_off, Bp + (size_t)(p2 * 8) * Nn);
        }
        asm volatile("cp.async.commit_group;" ::: "memory");

        int buf = s - (s / 3) * 3;
        const float* Ab = sp + buf * SGP_STAGE;          // [2][128][4]
        const float* Bb = Ab + 1024;                      // [8][128]

#pragma unroll
        for (int c = 0; c < 2; c++) {
            float4 a4[8];
#pragma unroll
            for (int i = 0; i < 8; i++)
                a4[i] = *(const float4*)(Ab + c * 512 + (ty * 8 + i) * 4);
#pragma unroll
            for (int t = 0; t < 4; t++) {
                int kk = c * 4 + t;
                float4 b0 = *(const float4*)(Bb + kk * 128 + tx * 8);
                float4 b1 = *(const float4*)(Bb + kk * 128 + tx * 8 + 4);
                float bv8[8] = {b0.x, b0.y, b0.z, b0.w, b1.x, b1.y, b1.z, b1.w};
#pragma unroll
                for (int i = 0; i < 8; i++) {
                    float a = (t == 0) ? a4[i].x : (t == 1) ? a4[i].y
                            : (t == 2) ? a4[i].z : a4[i].w;
#pragma unroll
                    for (int j = 0; j < 8; j++)
                        acc[i][j] = __fmaf_rn(a, bv8[j], acc[i][j]);
                }
            }
        }
    }

#pragma unroll
    for (int i = 0; i < 8; i++) {
        int row = mb + ty * 8 + i;
        float* Crow = Cm + (size_t)row * Nn + nb + tx * 8;
        const float* brow2 = bias + nb + tx * 8;
#pragma unroll
        for (int j = 0; j < 8; j++) {
            float v = __fadd_rn(acc[i][j], brow2[j]);
            if (RELU) v = fmaxf(v, 0.f);
            Crow[j] = v;
        }
    }
}

// ===========================================================================
// VQ stage A: fp16 m16n8k16 tensor screening (round-11 proven, verbatim)
// ===========================================================================
#define SCH_ST 68
#define SCH_LAT (64 * SCH_ST)
#define SCH_CB  (32 * SCH_ST)
#define SCH_SMEM ((SCH_LAT + 3 * SCH_CB) * 4)

__global__ __launch_bounds__(256, 2)
void k_vq_screen(const float* __restrict__ lat, const __half* __restrict__ cbh,
                 const float* __restrict__ cn,
                 unsigned short* __restrict__ cand, int* __restrict__ ccnt)
{
    extern __shared__ uint32_t smh[];
    uint32_t* Lw = smh;
    uint32_t* Cw = smh + SCH_LAT;
    __shared__ unsigned short s_cand[64 * CAPS];
    __shared__ float s_dv[64 * CAPS];
    __shared__ float s_minw[64][2];
    __shared__ int s_cnt[64];

    int tid = threadIdx.x;
    int lane = tid & 31, warp = tid >> 5;
    int wm = warp & 3, wn = warp >> 2;
    int g = lane >> 2, tg = lane & 3;
    int m0 = blockIdx.x * 64;

    if (tid < 64) s_cnt[tid] = 0;

    {
        int r = tid >> 2;
        int c0w = (tid & 3) * 16;
        const float4* src = (const float4*)(lat + (size_t)(m0 + r) * DDIM + (tid & 3) * 32);
        uint32_t* dst = Lw + r * SCH_ST + c0w;
#pragma unroll
        for (int i = 0; i < 8; i++) {
            float4 v = src[i];
            __half2 h0 = __floats2half2_rn(v.x, v.y);
            __half2 h1 = __floats2half2_rn(v.z, v.w);
            dst[i * 2] = *(uint32_t*)&h0;
            dst[i * 2 + 1] = *(uint32_t*)&h1;
        }
    }

    uint32_t sb = smem_u32(Cw);
    int cr = tid >> 3;
    int ck = tid & 7;

#pragma unroll
    for (int p = 0; p < 2; p++) {
        const __half* src = cbh + (size_t)(p * 32 + cr) * DDIM;
        uint32_t d = sb + (uint32_t)(p * SCH_CB + cr * SCH_ST) * 4;
        cp16(d + ck * 16, src + ck * 8);
        cp16(d + (ck + 8) * 16, src + (ck + 8) * 8);
        asm volatile("cp.async.commit_group;" ::: "memory");
    }

    float rmin0 = 3.4e38f, rmin1 = 3.4e38f;
    int r0 = wm * 16 + g, r1 = r0 + 8;
    const uint32_t* Ar0 = Lw + r0 * SCH_ST;
    const uint32_t* Ar1 = Lw + r1 * SCH_ST;

    for (int ch = 0; ch < 128; ch++) {
        asm volatile("cp.async.wait_group 1;" ::: "memory");
        __syncthreads();

        int p2 = ch + 2;
        if (p2 < 128) {
            int nbuf = p2 - (p2 / 3) * 3;
            const __half* src = cbh + (size_t)(p2 * 32 + cr) * DDIM;
            uint32_t d = sb + (uint32_t)(nbuf * SCH_CB + cr * SCH_ST) * 4;
            cp16(d + ck * 16, src + ck * 8);
            cp16(d + (ck + 8) * 16, src + (ck + 8) * 8);
        }
        asm volatile("cp.async.commit_group;" ::: "memory");

        int buf = ch - (ch / 3) * 3;
        const uint32_t* Cb = Cw + buf * SCH_CB;

        float acc[2][4];
#pragma unroll
        for (int ni = 0; ni < 2; ni++)
#pragma unroll
            for (int q = 0; q < 4; q++) acc[ni][q] = 0.f;

#pragma unroll
        for (int k8 = 0; k8 < 8; k8++) {
            int k0 = k8 * 8;
            uint32_t af[4];
            af[0] = Ar0[k0 + tg];
            af[1] = Ar1[k0 + tg];
            af[2] = Ar0[k0 + tg + 4];
            af[3] = Ar1[k0 + tg + 4];
#pragma unroll
            for (int ni = 0; ni < 2; ni++) {
                const uint32_t* Br = Cb + (wn * 16 + ni * 8 + g) * SCH_ST + k0;
                uint32_t bf[2] = {Br[tg], Br[tg + 4]};
                mma_f16(acc[ni], af, bf);
            }
        }

        float dv[2][4];
        int cbase[2];
        float dmin0 = 3.4e38f, dmin1 = 3.4e38f;
#pragma unroll
        for (int ni = 0; ni < 2; ni++) {
            int code0 = ch * 32 + wn * 16 + ni * 8 + tg * 2;
            float c0v = __ldg(cn + code0);
            float c1v = __ldg(cn + code0 + 1);
            dv[ni][0] = c0v - 2.f * acc[ni][0];
            dv[ni][1] = c1v - 2.f * acc[ni][1];
            dv[ni][2] = c0v - 2.f * acc[ni][2];
            dv[ni][3] = c1v - 2.f * acc[ni][3];
            cbase[ni] = code0;
            dmin0 = fminf(dmin0, fminf(dv[ni][0], dv[ni][1]));
            dmin1 = fminf(dmin1, fminf(dv[ni][2], dv[ni][3]));
        }
        dmin0 = fminf(dmin0, __shfl_xor_sync(0xffffffffu, dmin0, 1));
        dmin0 = fminf(dmin0, __shfl_xor_sync(0xffffffffu, dmin0, 2));
        dmin1 = fminf(dmin1, __shfl_xor_sync(0xffffffffu, dmin1, 1));
        dmin1 = fminf(dmin1, __shfl_xor_sync(0xffffffffu, dmin1, 2));
        rmin0 = fminf(rmin0, dmin0);
        rmin1 = fminf(rmin1, dmin1);
        float th0 = rmin0 + TAU, th1 = rmin1 + TAU;

#pragma unroll
        for (int ni = 0; ni < 2; ni++) {
#pragma unroll
            for (int h = 0; h < 2; h++) {
                float d0 = dv[ni][h];
                if (d0 <= th0) {
                    int s_ = atomicAdd(&s_cnt[r0], 1);
                    if (s_ < CAPS) {
                        s_cand[r0 * CAPS + s_] = (unsigned short)(cbase[ni] + h);
                        s_dv[r0 * CAPS + s_] = d0;
                    }
                }
                float d1 = dv[ni][h + 2];
                if (d1 <= th1) {
                    int s_ = atomicAdd(&s_cnt[r1], 1);
                    if (s_ < CAPS) {
                        s_cand[r1 * CAPS + s_] = (unsigned short)(cbase[ni] + h);
                        s_dv[r1 * CAPS + s_] = d1;
                    }
                }
            }
        }
    }

    __syncthreads();
    if (tg == 0) {
        s_minw[r0][wn] = rmin0;
        s_minw[r1][wn] = rmin1;
    }
    __syncthreads();

    if (tid < 64) {
        int r = tid;
        int n = s_cnt[r];
        if (n > CAPS) {
            ccnt[m0 + r] = n;
        } else {
            float th = fminf(s_minw[r][0], s_minw[r][1]) + TAU;
            int k = 0;
            for (int i = 0; i < n; i++) {
                if (s_dv[r * CAPS + i] <= th) {
                    s_cand[r * CAPS + k] = s_cand[r * CAPS + i];
                    k++;
                }
            }
            ccnt[m0 + r] = k;
        }
    }
    __syncthreads();

    for (int e = tid; e < 64 * CAPS; e += 256)
        cand[(size_t)m0 * CAPS + e] = s_cand[e];
}

// ===========================================================================
// VQ stage B: exact verification (round-9 proven; gq fp16 for decoder)
// ===========================================================================
__global__ __launch_bounds__(256)
void k_vq_exact(const float* __restrict__ lat, const float* __restrict__ cb,
                const float* __restrict__ cn, const float* __restrict__ ln,
                const unsigned short* __restrict__ cand,
                const int* __restrict__ ccnt,
                float* __restrict__ out, __half* __restrict__ gq,
                float* __restrict__ part)
{
    __shared__ float s_lat[8][128];
    __shared__ float s_part[8];
    int tid = threadIdx.x, lane = tid & 31, w = tid >> 5;
    int r = blockIdx.x * 8 + w;

    ((float4*)s_lat[w])[lane] = ((const float4*)(lat + (size_t)r * DDIM))[lane];
    __syncwarp();

    float Lr = ln[r];
    int cnt = ccnt[r];
    const float* lrow = s_lat[w];

    float bestv = 3.4e38f;
    int besti = 0x7FFFFFFF;

    if (cnt <= CAPS) {
        if (lane < cnt) {
            int code = cand[(size_t)r * CAPS + lane];
            const float4* c4 = (const float4*)(cb + (size_t)code * DDIM);
            float acc = 0.f;
#pragma unroll
            for (int i = 0; i < 32; i++) {
                float4 c = __ldg(c4 + i);
                acc = __fmaf_rn(lrow[i * 4 + 0], c.x, acc);
                acc = __fmaf_rn(lrow[i * 4 + 1], c.y, acc);
                acc = __fmaf_rn(lrow[i * 4 + 2], c.z, acc);
                acc = __fmaf_rn(lrow[i * 4 + 3], c.w, acc);
            }
            bestv = __fsub_rn(__fadd_rn(Lr, __ldg(cn + code)),
                              __fmul_rn(2.f, acc));
            besti = code;
        }
    } else {
        for (int c0 = lane; c0 < KCB; c0 += 32) {
            const float4* c4 = (const float4*)(cb + (size_t)c0 * DDIM);
            float acc = 0.f;
#pragma unroll 8
            for (int i = 0; i < 32; i++) {
                float4 c = __ldg(c4 + i);
                acc = __fmaf_rn(lrow[i * 4 + 0], c.x, acc);
                acc = __fmaf_rn(lrow[i * 4 + 1], c.y, acc);
                acc = __fmaf_rn(lrow[i * 4 + 2], c.z, acc);
                acc = __fmaf_rn(lrow[i * 4 + 3], c.w, acc);
            }
            float dist = __fsub_rn(__fadd_rn(Lr, __ldg(cn + c0)),
                                   __fmul_rn(2.f, acc));
            if (dist < bestv || (dist == bestv && c0 < besti)) {
                bestv = dist; besti = c0;
            }
        }
    }

#pragma unroll
    for (int o = 16; o >= 1; o >>= 1) {
        float ov = __shfl_xor_sync(0xffffffffu, bestv, o);
        int oi = __shfl_xor_sync(0xffffffffu, besti, o);
        if (ov < bestv || (ov == bestv && oi < besti)) { bestv = ov; besti = oi; }
    }

    if (lane == 0) out[OUT_INDS + r] = (float)besti;

    const float* qrow = cb + (size_t)besti * DDIM;
    float lsum = 0.f;
#pragma unroll
    for (int i = 0; i < 4; i++) {
        int d = lane + i * 32;
        float l = lrow[d], q = qrow[d];
        float qmL = q - l;
        float qst = l + qmL;
        out[OUT_Q + (size_t)r * DDIM + d] = qst;
        gq[(size_t)r * DDIM + d] = __float2half_rn(qst);
        lsum += qmL * qmL;
    }
#pragma unroll
    for (int o = 16; o >= 1; o >>= 1)
        lsum += __shfl_xor_sync(0xffffffffu, lsum, o);
    if (lane == 0) s_part[w] = lsum;
    __syncthreads();
    if (tid == 0) {
        float s = 0.f;
        for (int i = 0; i < 8; i++) s += s_part[i];
        part[blockIdx.x] = s;
    }
}

// ---------------------------------------------------------------------------
// Weight transpose + fp16 convert: out[c][r] = fp16(in[r][c])
// ---------------------------------------------------------------------------
__global__ void k_transpose(const float* __restrict__ in, __half* __restrict__ out,
                            int R, int C)
{
    __shared__ float t[32][33];
    int c0 = blockIdx.x * 32, r0 = blockIdx.y * 32;
    int x = threadIdx.x, y0 = threadIdx.y;
#pragma unroll
    for (int dy = 0; dy < 32; dy += 8)
        t[y0 + dy][x] = in[(r0 + y0 + dy) * C + c0 + x];
    __syncthreads();
#pragma unroll
    for (int dy = 0; dy < 32; dy += 8)
        out[(c0 + y0 + dy) * R + r0 + x] = __float2half_rn(t[x][y0 + dy]);
}

// ===========================================================================
// tc_gemm_f16 (round-12 proven): fp16 m16n8k16 GEMM, cp.async 3-stage ring.
// ===========================================================================
#define TCH_ST 36
#define TCH_TILE (128 * TCH_ST)
#define TCH_SMEM (3 * 2 * TCH_TILE * 4)

template <int OUT16>
__global__ __launch_bounds__(256, 2)
void tc_gemm_f16(const __half* __restrict__ Am, const __half* __restrict__ Bt,
                 const float* __restrict__ bias, void* __restrict__ Cout,
                 int Nn, int Kk)
{
    extern __shared__ uint32_t smw[];
    uint32_t sbase = smem_u32(smw);

    int tid = threadIdx.x;
    int lane = tid & 31, warp = tid >> 5;
    int wm = warp & 3, wn = warp >> 2;
    int g = lane >> 2, tg = lane & 3;
    int mb = blockIdx.y * 128, nb = blockIdx.x * 128;

    int lr = tid >> 1;
    int lhh = (tid & 1) * 32;
    int lhw = (tid & 1) * 16;

    const __half* Ap = Am + (size_t)(mb + lr) * Kk + lhh;
    const __half* Bp = Bt + (size_t)(nb + lr) * Kk + lhh;
    uint32_t stg_off = (uint32_t)(lr * TCH_ST + lhw) * 4;

    float acc[2][8][4];
#pragma unroll
    for (int mi = 0; mi < 2; mi++)
#pragma unroll
        for (int ni = 0; ni < 8; ni++)
#pragma unroll
            for (int q = 0; q < 4; q++) acc[mi][ni][q] = 0.f;

    int NC = Kk >> 6;

#pragma unroll
    for (int p = 0; p < 2; p++) {
        uint32_t da = sbase + (uint32_t)(p * 2 * TCH_TILE) * 4 + stg_off;
        uint32_t db = da + (uint32_t)TCH_TILE * 4;
        const __half* sa = Ap + p * 64;
        const __half* sb = Bp + p * 64;
#pragma unroll
        for (int i = 0; i < 4; i++) {
            cp16(da + i * 16, sa + i * 8);
            cp16(db + i * 16, sb + i * 8);
        }
        asm volatile("cp.async.commit_group;" ::: "memory");
    }

    for (int s = 0; s < NC; s++) {
        asm volatile("cp.async.wait_group 1;" ::: "memory");
        __syncthreads();

        int p2 = s + 2;
        if (p2 < NC) {
            int nbuf = p2 - (p2 / 3) * 3;
            uint32_t da = sbase + (uint32_t)(nbuf * 2 * TCH_TILE) * 4 + stg_off;
            uint32_t db = da + (uint32_t)TCH_TILE * 4;
            const __half* sa = Ap + p2 * 64;
            const __half* sb = Bp + p2 * 64;
#pragma unroll
            for (int i = 0; i < 4; i++) {
                cp16(da + i * 16, sa + i * 8);
                cp16(db + i * 16, sb + i * 8);
            }
        }
        asm volatile("cp.async.commit_group;" ::: "memory");

        int buf = s - (s / 3) * 3;
        const uint32_t* Ab = smw + buf * 2 * TCH_TILE;
        const uint32_t* Bb = Ab + TCH_TILE;
#pragma unroll
        for (int k16 = 0; k16 < 4; k16++) {
            int k0 = k16 * 8;
            uint32_t af[2][4], bf[8][2];
#pragma unroll
            for (int mi = 0; mi < 2; mi++) {
                int r = wm * 32 + mi * 16 + g;
                af[mi][0] = Ab[r * TCH_ST + k0 + tg];
                af[mi][1] = Ab[(r + 8) * TCH_ST + k0 + tg];
                af[mi][2] = Ab[r * TCH_ST + k0 + tg + 4];
                af[mi][3] = Ab[(r + 8) * TCH_ST + k0 + tg + 4];
            }
#pragma unroll
            for (int ni = 0; ni < 8; ni++) {
                int n = wn * 64 + ni * 8 + g;
                bf[ni][0] = Bb[n * TCH_ST + k0 + tg];
                bf[ni][1] = Bb[n * TCH_ST + k0 + tg + 4];
            }
#pragma unroll
            for (int mi = 0; mi < 2; mi++)
#pragma unroll
                for (int ni = 0; ni < 8; ni++)
                    mma_f16(acc[mi][ni], af[mi], bf[ni]);
        }
    }

#pragma unroll
    for (int mi = 0; mi < 2; mi++) {
        int row = mb + wm * 32 + mi * 16 + g;
#pragma unroll
        for (int ni = 0; ni < 8; ni++) {
            int col = nb + wn * 64 + ni * 8 + tg * 2;
            float b0 = __ldg(bias + col), b1 = __ldg(bias + col + 1);
            float v0 = fmaxf(acc[mi][ni][0] + b0, 0.f);
            float v1 = fmaxf(acc[mi][ni][1] + b1, 0.f);
            float v2 = fmaxf(acc[mi][ni][2] + b0, 0.f);
            float v3 = fmaxf(acc[mi][ni][3] + b1, 0.f);
            if (OUT16) {
                __half* Cm = (__half*)Cout;
                __half2 h01 = __floats2half2_rn(v0, v1);
                __half2 h23 = __floats2half2_rn(v2, v3);
                *(__half2*)(Cm + (size_t)row * Nn + col) = h01;
                *(__half2*)(Cm + (size_t)(row + 8) * Nn + col) = h23;
            } else {
                float* Cm = (float*)Cout;
                *(float2*)(Cm + (size_t)row * Nn + col) = make_float2(v0, v1);
                *(float2*)(Cm + (size_t)(row + 8) * Nn + col) = make_float2(v2, v3);
            }
        }
    }
}

// ---------------------------------------------------------------------------
// Decoder layer 3: recons = tanh(d2 @ Wd3 + bd3). Warp per row; Wd3 staged
// in smem (identical accumulation order -> bit-identical recons).
// ---------------------------------------------------------------------------
__global__ void k_dec3(const float* __restrict__ d2, const float* __restrict__ Wd3,
                       const float* __restrict__ bd3, float* __restrict__ out)
{
    __shared__ float ws[HDIM * ADIM];    // 24KB
    int tid = threadIdx.x;
    for (int e = tid; e < HDIM * ADIM; e += 256)
        ws[e] = Wd3[e];
    __syncthreads();

    int warp = (blockIdx.x * 256 + tid) >> 5;
    int lane = tid & 31;
    const float* row = d2 + (size_t)warp * HDIM;
    float a0 = 0.f, a1 = 0.f, a2 = 0.f, a3 = 0.f, a4 = 0.f, a5 = 0.f;
#pragma unroll 4
    for (int k = lane; k < HDIM; k += 32) {
        float v = row[k];
        const float* w = ws + k * ADIM;
        a0 += v * w[0]; a1 += v * w[1]; a2 += v * w[2];
        a3 += v * w[3]; a4 += v * w[4]; a5 += v * w[5];
    }
#pragma unroll
    for (int off = 16; off; off >>= 1) {
        a0 += __shfl_xor_sync(0xffffffffu, a0, off);
        a1 += __shfl_xor_sync(0xffffffffu, a1, off);
        a2 += __shfl_xor_sync(0xffffffffu, a2, off);
        a3 += __shfl_xor_sync(0xffffffffu, a3, off);
        a4 += __shfl_xor_sync(0xffffffffu, a4, off);
        a5 += __shfl_xor_sync(0xffffffffu, a5, off);
    }
    if (lane == 0) {
        float* o = out + OUT_REC + (size_t)warp * ADIM;
        o[0] = tanhf(a0 + bd3[0]);
        o[1] = tanhf(a1 + bd3[1]);
        o[2] = tanhf(a2 + bd3[2]);
        o[3] = tanhf(a3 + bd3[3]);
        o[4] = tanhf(a4 + bd3[4]);
        o[5] = tanhf(a5 + bd3[5]);
    }
}

// ---------------------------------------------------------------------------
// Final loss reduction (4096 partials)
// ---------------------------------------------------------------------------
__global__ void k_loss(const float* __restrict__ part, float* __restrict__ out)
{
    __shared__ float s[256];
    int tid = threadIdx.x;
    float a = 0.f;
    for (int i = 0; i < 16; i++) a += part[tid + 256 * i];
    s[tid] = a;
    __syncthreads();
    for (int st = 128; st > 0; st >>= 1) {
        if (tid < st) s[tid] += s[tid + st];
        __syncthreads();
    }
    if (tid == 0)
        out[OUT_LOSS] = 1.25f * s[0] / (float)(NTOK * DDIM);
}

// ---------------------------------------------------------------------------
extern "C" void kernel_launch(void* const* d_in, const int* in_sizes, int n_in,
                              void* d_out, int out_size)
{
    const float* action = (const float*)d_in[0];
    const float* W1   = (const float*)d_in[1];
    const float* b1   = (const float*)d_in[2];
    const float* W2   = (const float*)d_in[3];
    const float* b2   = (const float*)d_in[4];
    const float* Wmu  = (const float*)d_in[5];
    const float* bmu  = (const float*)d_in[6];
    const float* cb   = (const float*)d_in[7];
    const float* Wd1  = (const float*)d_in[8];
    const float* bd1  = (const float*)d_in[9];
    const float* Wd2  = (const float*)d_in[10];
    const float* bd2  = (const float*)d_in[11];
    const float* Wd3  = (const float*)d_in[12];
    const float* bd3  = (const float*)d_in[13];
    float* out = (float*)d_out;

    float *p_h1, *p_h2, *p_lat, *p_ln, *p_cn, *p_part;
    __half *p_cbh, *p_h1h, *p_qh, *p_wt1, *p_wt2;
    unsigned short* p_cand;
    int* p_ccnt;
    cudaGetSymbolAddress((void**)&p_h1, g_h1);
    cudaGetSymbolAddress((void**)&p_h1h, g_h1h);
    cudaGetSymbolAddress((void**)&p_h2, g_h2);
    cudaGetSymbolAddress((void**)&p_lat, g_lat);
    cudaGetSymbolAddress((void**)&p_qh, g_qh);
    cudaGetSymbolAddress((void**)&p_ln, g_ln);
    cudaGetSymbolAddress((void**)&p_cn, g_cn);
    cudaGetSymbolAddress((void**)&p_cbh, g_cbh);
    cudaGetSymbolAddress((void**)&p_part, g_part);
    cudaGetSymbolAddress((void**)&p_wt1, g_wt1);
    cudaGetSymbolAddress((void**)&p_wt2, g_wt2);
    cudaGetSymbolAddress((void**)&p_cand, g_cand);
    cudaGetSymbolAddress((void**)&p_ccnt, g_ccnt);

    cudaFuncSetAttribute(tc_gemm_f16<1>, cudaFuncAttributeMaxDynamicSharedMemorySize,
                         TCH_SMEM);
    cudaFuncSetAttribute(tc_gemm_f16<0>, cudaFuncAttributeMaxDynamicSharedMemorySize,
                         TCH_SMEM);
    cudaFuncSetAttribute(k_vq_screen, cudaFuncAttributeMaxDynamicSharedMemorySize,
                         SCH_SMEM);

    // weight transposes (fp16) + codebook norms + fp16 codebook
    k_transpose<<<dim3(HDIM / 32, DDIM / 32), dim3(32, 8)>>>(Wd1, p_wt1, DDIM, HDIM);
    k_transpose<<<dim3(HDIM / 32, HDIM / 32), dim3(32, 8)>>>(Wd2, p_wt2, HDIM, HDIM);
    k_cnorm<<<KCB / 8, 256>>>(cb, p_cn, p_cbh);

    // encoder (fp32-exact — argmin-critical; cp.async-pipelined schedule)
    k_enc1<<<(NTOK * HDIM) / 1024, 256>>>(action, W1, b1, p_h1);
    sgemm<1><<<dim3(HDIM / 128, NTOK / 128), 256>>>(p_h1, W2, b2, p_h2, NTOK, HDIM, HDIM);
    sgemm<0><<<dim3(DDIM / 128, NTOK / 128), 256>>>(p_h2, Wmu, bmu, p_lat, NTOK, DDIM, HDIM);
    k_rownorm<<<NTOK / 8, 256>>>(p_lat, p_ln);

    // vector quantization: fp16 tensor screening + tiny exact verify
    k_vq_screen<<<NTOK / 64, 256, SCH_SMEM>>>(p_lat, p_cbh, p_cn, p_cand, p_ccnt);
    k_vq_exact<<<VQ2_BLOCKS, 256>>>(p_lat, cb, p_cn, p_ln, p_cand, p_ccnt,
                                    out, p_qh, p_part);

    // decoder (fp16 tensor-core, cp.async pipelined)
    tc_gemm_f16<1><<<dim3(HDIM / 128, NTOK / 128), 256, TCH_SMEM>>>(p_qh, p_wt1, bd1, p_h1h, HDIM, DDIM);
    tc_gemm_f16<0><<<dim3(HDIM / 128, NTOK / 128), 256, TCH_SMEM>>>(p_h1h, p_wt2, bd2, p_h2, HDIM, HDIM);
    k_dec3<<<NTOK / 8, 256>>>(p_h2, Wd3, bd3, out);

    // scalar loss
    k_loss<<<1, 256>>>(p_part, out);
}

// round 15
// speedup vs baseline: 1.0065x; 1.0065x over previous
#include <cuda_runtime.h>
#include <cuda_fp16.h>
#include <math.h>
#include <stdint.h>

// Problem dims
#define NTOK 32768
#define ADIM 6
#define HDIM 1024
#define DDIM 128
#define KCB  4096

// Output layout (float32, concatenated in reference-return order)
#define OUT_INDS 0
#define OUT_Q    (NTOK)
#define OUT_REC  (NTOK + NTOK * DDIM)
#define OUT_LOSS (NTOK + NTOK * DDIM + NTOK * ADIM)

#define CAPS 64
#define TAU 8e-6f
#define VQ2_BLOCKS (NTOK / 8)   // 4096

// -------- scratch (device globals; no runtime allocation) --------
__device__ float g_h1[NTOK * HDIM];
__device__ float g_h2[NTOK * HDIM];    // fp32 h2 (precision-critical for out2)
__device__ __half g_h1h[NTOK * HDIM];  // fp16 h1 (decoder intermediate)
__device__ float g_lat[NTOK * DDIM];
__device__ __half g_qh[NTOK * DDIM];   // fp16 quantized_st (decoder input)
__device__ float g_ln[NTOK];
__device__ float g_cn[KCB];
__device__ __half g_cbh[KCB * DDIM];   // fp16 codebook (screen only)
__device__ float g_part[VQ2_BLOCKS];
__device__ __half g_wt1[HDIM * DDIM];  // Wd1^T fp16
__device__ __half g_wt2[HDIM * HDIM];  // Wd2^T fp16
__device__ unsigned short g_cand[NTOK * CAPS];
__device__ int g_ccnt[NTOK];

__device__ __forceinline__ uint32_t smem_u32(const void* p)
{
    uint32_t a;
    asm("{ .reg .u64 t; cvta.to.shared.u64 t, %1; cvt.u32.u64 %0, t; }"
        : "=r"(a) : "l"(p));
    return a;
}
__device__ __forceinline__ void cp16(uint32_t dst, const void* src)
{
    asm volatile("cp.async.cg.shared.global [%0], [%1], 16;"
                 :: "r"(dst), "l"(src) : "memory");
}
__device__ __forceinline__ void mma_f16(float* c, const uint32_t* a, const uint32_t* b)
{
    asm("mma.sync.aligned.m16n8k16.row.col.f32.f16.f16.f32 "
        "{%0,%1,%2,%3}, {%4,%5,%6,%7}, {%8,%9}, {%0,%1,%2,%3};"
        : "+f"(c[0]), "+f"(c[1]), "+f"(c[2]), "+f"(c[3])
        : "r"(a[0]), "r"(a[1]), "r"(a[2]), "r"(a[3]), "r"(b[0]), "r"(b[1]));
}

// ---------------------------------------------------------------------------
// Codebook norms + fp16 codebook (XLA-order reduction, argmin-tie critical)
// ---------------------------------------------------------------------------
__global__ void k_cnorm(const float* __restrict__ cb, float* __restrict__ cn,
                        __half* __restrict__ cbh)
{
    int w = (blockIdx.x * blockDim.x + threadIdx.x) >> 5;
    int lane = threadIdx.x & 31;
    const float* row = cb + w * DDIM;
    __half* hrow = cbh + (size_t)w * DDIM;
    float acc = 0.f;
#pragma unroll
    for (int i = 0; i < 4; i++) {
        float v = row[lane + i * 32];
        hrow[lane + i * 32] = __float2half_rn(v);
        acc = __fadd_rn(acc, __fmul_rn(v, v));
    }
#pragma unroll
    for (int off = 16; off >= 1; off >>= 1)
        acc = __fadd_rn(acc, __shfl_down_sync(0xffffffffu, acc, off));
    if (lane == 0) cn[w] = acc;
}

__global__ void k_rownorm(const float* __restrict__ lat, float* __restrict__ ln)
{
    int w = (blockIdx.x * blockDim.x + threadIdx.x) >> 5;
    int lane = threadIdx.x & 31;
    const float* row = lat + w * DDIM;
    float acc = 0.f;
#pragma unroll
    for (int i = 0; i < 4; i++) {
        float v = row[lane + i * 32];
        acc = __fadd_rn(acc, __fmul_rn(v, v));
    }
#pragma unroll
    for (int off = 16; off >= 1; off >>= 1)
        acc = __fadd_rn(acc, __shfl_down_sync(0xffffffffu, acc, off));
    if (lane == 0) ln[w] = acc;
}

// ---------------------------------------------------------------------------
// Encoder layer 1 (A=6), 4 outputs/thread (round-11 proven)
// ---------------------------------------------------------------------------
__global__ void k_enc1(const float* __restrict__ act, const float* __restrict__ W1,
                       const float* __restrict__ b1, float* __restrict__ h1)
{
    int gid = blockIdx.x * blockDim.x + threadIdx.x;
    int n = gid >> 8;
    int h = (gid & 255) * 4;
    const float* a = act + n * ADIM;
    float av[ADIM];
#pragma unroll
    for (int k = 0; k < ADIM; k++) av[k] = a[k];
    float4 s = make_float4(0.f, 0.f, 0.f, 0.f);
#pragma unroll
    for (int k = 0; k < ADIM; k++) {
        float4 w = *(const float4*)(W1 + k * HDIM + h);
        s.x = __fmaf_rn(av[k], w.x, s.x);
        s.y = __fmaf_rn(av[k], w.y, s.y);
        s.z = __fmaf_rn(av[k], w.z, s.z);
        s.w = __fmaf_rn(av[k], w.w, s.w);
    }
    float4 b = *(const float4*)(b1 + h);
    s.x = fmaxf(__fadd_rn(s.x, b.x), 0.f);
    s.y = fmaxf(__fadd_rn(s.y, b.y), 0.f);
    s.z = fmaxf(__fadd_rn(s.z, b.z), 0.f);
    s.w = fmaxf(__fadd_rn(s.w, b.w), 0.f);
    *(float4*)(h1 + (size_t)n * HDIM + h) = s;
}

// ---------------------------------------------------------------------------
// FP32 SGEMM (round-3 proven) — ENCODER ONLY (argmin-critical path)
// ---------------------------------------------------------------------------
template <int RELU>
__global__ __launch_bounds__(256)
void sgemm(const float* __restrict__ Am, const float* __restrict__ Bm,
           const float* __restrict__ bias, float* __restrict__ Cm,
           int M, int Nn, int Kk)
{
    __shared__ float As[8][128];
    __shared__ float Bs[8][128];

    int tid = threadIdx.x;
    int tx = tid & 15;
    int ty = tid >> 4;
    int mb = blockIdx.y * 128;
    int nb = blockIdx.x * 128;

    int arow = tid >> 1;
    int acol = (tid & 1) * 4;
    int brow = tid >> 5;
    int bcol = (tid & 31) * 4;

    const float* Aptr = Am + (mb + arow) * Kk + acol;
    const float* Bptr = Bm + brow * Nn + nb + bcol;

    float acc[8][8];
#pragma unroll
    for (int i = 0; i < 8; i++)
#pragma unroll
        for (int j = 0; j < 8; j++) acc[i][j] = 0.f;

    for (int k0 = 0; k0 < Kk; k0 += 8) {
        float4 av = *(const float4*)Aptr;
        As[acol + 0][arow] = av.x;
        As[acol + 1][arow] = av.y;
        As[acol + 2][arow] = av.z;
        As[acol + 3][arow] = av.w;
        *(float4*)&Bs[brow][bcol] = *(const float4*)Bptr;
        __syncthreads();

#pragma unroll
        for (int kk = 0; kk < 8; kk++) {
            float4 a0 = *(const float4*)&As[kk][ty * 8];
            float4 a1 = *(const float4*)&As[kk][ty * 8 + 4];
            float4 b0 = *(const float4*)&Bs[kk][tx * 8];
            float4 b1 = *(const float4*)&Bs[kk][tx * 8 + 4];
            float av8[8] = {a0.x, a0.y, a0.z, a0.w, a1.x, a1.y, a1.z, a1.w};
            float bv8[8] = {b0.x, b0.y, b0.z, b0.w, b1.x, b1.y, b1.z, b1.w};
#pragma unroll
            for (int i = 0; i < 8; i++)
#pragma unroll
                for (int j = 0; j < 8; j++)
                    acc[i][j] = __fmaf_rn(av8[i], bv8[j], acc[i][j]);
        }
        __syncthreads();
        Aptr += 8;
        Bptr += 8 * Nn;
    }

#pragma unroll
    for (int i = 0; i < 8; i++) {
        int row = mb + ty * 8 + i;
        float* Crow = Cm + row * Nn + nb + tx * 8;
        const float* brow2 = bias + nb + tx * 8;
#pragma unroll
        for (int j = 0; j < 8; j++) {
            float v = __fadd_rn(acc[i][j], brow2[j]);
            if (RELU) v = fmaxf(v, 0.f);
            Crow[j] = v;
        }
    }
}

// ===========================================================================
// VQ stage A: fp16 m16n8k16 tensor screening (round-11 proven, verbatim)
// ===========================================================================
#define SCH_ST 68
#define SCH_LAT (64 * SCH_ST)
#define SCH_CB  (32 * SCH_ST)
#define SCH_SMEM ((SCH_LAT + 3 * SCH_CB) * 4)

__global__ __launch_bounds__(256, 2)
void k_vq_screen(const float* __restrict__ lat, const __half* __restrict__ cbh,
                 const float* __restrict__ cn,
                 unsigned short* __restrict__ cand, int* __restrict__ ccnt)
{
    extern __shared__ uint32_t smh[];
    uint32_t* Lw = smh;
    uint32_t* Cw = smh + SCH_LAT;
    __shared__ unsigned short s_cand[64 * CAPS];
    __shared__ float s_dv[64 * CAPS];
    __shared__ float s_minw[64][2];
    __shared__ int s_cnt[64];

    int tid = threadIdx.x;
    int lane = tid & 31, warp = tid >> 5;
    int wm = warp & 3, wn = warp >> 2;
    int g = lane >> 2, tg = lane & 3;
    int m0 = blockIdx.x * 64;

    if (tid < 64) s_cnt[tid] = 0;

    {
        int r = tid >> 2;
        int c0w = (tid & 3) * 16;
        const float4* src = (const float4*)(lat + (size_t)(m0 + r) * DDIM + (tid & 3) * 32);
        uint32_t* dst = Lw + r * SCH_ST + c0w;
#pragma unroll
        for (int i = 0; i < 8; i++) {
            float4 v = src[i];
            __half2 h0 = __floats2half2_rn(v.x, v.y);
            __half2 h1 = __floats2half2_rn(v.z, v.w);
            dst[i * 2] = *(uint32_t*)&h0;
            dst[i * 2 + 1] = *(uint32_t*)&h1;
        }
    }

    uint32_t sb = smem_u32(Cw);
    int cr = tid >> 3;
    int ck = tid & 7;

#pragma unroll
    for (int p = 0; p < 2; p++) {
        const __half* src = cbh + (size_t)(p * 32 + cr) * DDIM;
        uint32_t d = sb + (uint32_t)(p * SCH_CB + cr * SCH_ST) * 4;
        cp16(d + ck * 16, src + ck * 8);
        cp16(d + (ck + 8) * 16, src + (ck + 8) * 8);
        asm volatile("cp.async.commit_group;" ::: "memory");
    }

    float rmin0 = 3.4e38f, rmin1 = 3.4e38f;
    int r0 = wm * 16 + g, r1 = r0 + 8;
    const uint32_t* Ar0 = Lw + r0 * SCH_ST;
    const uint32_t* Ar1 = Lw + r1 * SCH_ST;

    for (int ch = 0; ch < 128; ch++) {
        asm volatile("cp.async.wait_group 1;" ::: "memory");
        __syncthreads();

        int p2 = ch + 2;
        if (p2 < 128) {
            int nbuf = p2 - (p2 / 3) * 3;
            const __half* src = cbh + (size_t)(p2 * 32 + cr) * DDIM;
            uint32_t d = sb + (uint32_t)(nbuf * SCH_CB + cr * SCH_ST) * 4;
            cp16(d + ck * 16, src + ck * 8);
            cp16(d + (ck + 8) * 16, src + (ck + 8) * 8);
        }
        asm volatile("cp.async.commit_group;" ::: "memory");

        int buf = ch - (ch / 3) * 3;
        const uint32_t* Cb = Cw + buf * SCH_CB;

        float acc[2][4];
#pragma unroll
        for (int ni = 0; ni < 2; ni++)
#pragma unroll
            for (int q = 0; q < 4; q++) acc[ni][q] = 0.f;

#pragma unroll
        for (int k8 = 0; k8 < 8; k8++) {
            int k0 = k8 * 8;
            uint32_t af[4];
            af[0] = Ar0[k0 + tg];
            af[1] = Ar1[k0 + tg];
            af[2] = Ar0[k0 + tg + 4];
            af[3] = Ar1[k0 + tg + 4];
#pragma unroll
            for (int ni = 0; ni < 2; ni++) {
                const uint32_t* Br = Cb + (wn * 16 + ni * 8 + g) * SCH_ST + k0;
                uint32_t bf[2] = {Br[tg], Br[tg + 4]};
                mma_f16(acc[ni], af, bf);
            }
        }

        float dv[2][4];
        int cbase[2];
        float dmin0 = 3.4e38f, dmin1 = 3.4e38f;
#pragma unroll
        for (int ni = 0; ni < 2; ni++) {
            int code0 = ch * 32 + wn * 16 + ni * 8 + tg * 2;
            float c0v = __ldg(cn + code0);
            float c1v = __ldg(cn + code0 + 1);
            dv[ni][0] = c0v - 2.f * acc[ni][0];
            dv[ni][1] = c1v - 2.f * acc[ni][1];
            dv[ni][2] = c0v - 2.f * acc[ni][2];
            dv[ni][3] = c1v - 2.f * acc[ni][3];
            cbase[ni] = code0;
            dmin0 = fminf(dmin0, fminf(dv[ni][0], dv[ni][1]));
            dmin1 = fminf(dmin1, fminf(dv[ni][2], dv[ni][3]));
        }
        dmin0 = fminf(dmin0, __shfl_xor_sync(0xffffffffu, dmin0, 1));
        dmin0 = fminf(dmin0, __shfl_xor_sync(0xffffffffu, dmin0, 2));
        dmin1 = fminf(dmin1, __shfl_xor_sync(0xffffffffu, dmin1, 1));
        dmin1 = fminf(dmin1, __shfl_xor_sync(0xffffffffu, dmin1, 2));
        rmin0 = fminf(rmin0, dmin0);
        rmin1 = fminf(rmin1, dmin1);
        float th0 = rmin0 + TAU, th1 = rmin1 + TAU;

#pragma unroll
        for (int ni = 0; ni < 2; ni++) {
#pragma unroll
            for (int h = 0; h < 2; h++) {
                float d0 = dv[ni][h];
                if (d0 <= th0) {
                    int s_ = atomicAdd(&s_cnt[r0], 1);
                    if (s_ < CAPS) {
                        s_cand[r0 * CAPS + s_] = (unsigned short)(cbase[ni] + h);
                        s_dv[r0 * CAPS + s_] = d0;
                    }
                }
                float d1 = dv[ni][h + 2];
                if (d1 <= th1) {
                    int s_ = atomicAdd(&s_cnt[r1], 1);
                    if (s_ < CAPS) {
                        s_cand[r1 * CAPS + s_] = (unsigned short)(cbase[ni] + h);
                        s_dv[r1 * CAPS + s_] = d1;
                    }
                }
            }
        }
    }

    __syncthreads();
    if (tg == 0) {
        s_minw[r0][wn] = rmin0;
        s_minw[r1][wn] = rmin1;
    }
    __syncthreads();

    if (tid < 64) {
        int r = tid;
        int n = s_cnt[r];
        if (n > CAPS) {
            ccnt[m0 + r] = n;
        } else {
            float th = fminf(s_minw[r][0], s_minw[r][1]) + TAU;
            int k = 0;
            for (int i = 0; i < n; i++) {
                if (s_dv[r * CAPS + i] <= th) {
                    s_cand[r * CAPS + k] = s_cand[r * CAPS + i];
                    k++;
                }
            }
            ccnt[m0 + r] = k;
        }
    }
    __syncthreads();

    for (int e = tid; e < 64 * CAPS; e += 256)
        cand[(size_t)m0 * CAPS + e] = s_cand[e];
}

// ===========================================================================
// VQ stage B: exact verification (round-9 proven; gq fp16 for decoder)
// ===========================================================================
__global__ __launch_bounds__(256)
void k_vq_exact(const float* __restrict__ lat, const float* __restrict__ cb,
                const float* __restrict__ cn, const float* __restrict__ ln,
                const unsigned short* __restrict__ cand,
                const int* __restrict__ ccnt,
                float* __restrict__ out, __half* __restrict__ gq,
                float* __restrict__ part)
{
    __shared__ float s_lat[8][128];
    __shared__ float s_part[8];
    int tid = threadIdx.x, lane = tid & 31, w = tid >> 5;
    int r = blockIdx.x * 8 + w;

    ((float4*)s_lat[w])[lane] = ((const float4*)(lat + (size_t)r * DDIM))[lane];
    __syncwarp();

    float Lr = ln[r];
    int cnt = ccnt[r];
    const float* lrow = s_lat[w];

    float bestv = 3.4e38f;
    int besti = 0x7FFFFFFF;

    if (cnt <= CAPS) {
        if (lane < cnt) {
            int code = cand[(size_t)r * CAPS + lane];
            const float4* c4 = (const float4*)(cb + (size_t)code * DDIM);
            float acc = 0.f;
#pragma unroll
            for (int i = 0; i < 32; i++) {
                float4 c = __ldg(c4 + i);
                acc = __fmaf_rn(lrow[i * 4 + 0], c.x, acc);
                acc = __fmaf_rn(lrow[i * 4 + 1], c.y, acc);
                acc = __fmaf_rn(lrow[i * 4 + 2], c.z, acc);
                acc = __fmaf_rn(lrow[i * 4 + 3], c.w, acc);
            }
            bestv = __fsub_rn(__fadd_rn(Lr, __ldg(cn + code)),
                              __fmul_rn(2.f, acc));
            besti = code;
        }
    } else {
        for (int c0 = lane; c0 < KCB; c0 += 32) {
            const float4* c4 = (const float4*)(cb + (size_t)c0 * DDIM);
            float acc = 0.f;
#pragma unroll 8
            for (int i = 0; i < 32; i++) {
                float4 c = __ldg(c4 + i);
                acc = __fmaf_rn(lrow[i * 4 + 0], c.x, acc);
                acc = __fmaf_rn(lrow[i * 4 + 1], c.y, acc);
                acc = __fmaf_rn(lrow[i * 4 + 2], c.z, acc);
                acc = __fmaf_rn(lrow[i * 4 + 3], c.w, acc);
            }
            float dist = __fsub_rn(__fadd_rn(Lr, __ldg(cn + c0)),
                                   __fmul_rn(2.f, acc));
            if (dist < bestv || (dist == bestv && c0 < besti)) {
                bestv = dist; besti = c0;
            }
        }
    }

#pragma unroll
    for (int o = 16; o >= 1; o >>= 1) {
        float ov = __shfl_xor_sync(0xffffffffu, bestv, o);
        int oi = __shfl_xor_sync(0xffffffffu, besti, o);
        if (ov < bestv || (ov == bestv && oi < besti)) { bestv = ov; besti = oi; }
    }

    if (lane == 0) out[OUT_INDS + r] = (float)besti;

    const float* qrow = cb + (size_t)besti * DDIM;
    float lsum = 0.f;
#pragma unroll
    for (int i = 0; i < 4; i++) {
        int d = lane + i * 32;
        float l = lrow[d], q = qrow[d];
        float qmL = q - l;
        float qst = l + qmL;
        out[OUT_Q + (size_t)r * DDIM + d] = qst;
        gq[(size_t)r * DDIM + d] = __float2half_rn(qst);
        lsum += qmL * qmL;
    }
#pragma unroll
    for (int o = 16; o >= 1; o >>= 1)
        lsum += __shfl_xor_sync(0xffffffffu, lsum, o);
    if (lane == 0) s_part[w] = lsum;
    __syncthreads();
    if (tid == 0) {
        float s = 0.f;
        for (int i = 0; i < 8; i++) s += s_part[i];
        part[blockIdx.x] = s;
    }
}

// ---------------------------------------------------------------------------
// Weight transpose + fp16 convert: out[c][r] = fp16(in[r][c])
// ---------------------------------------------------------------------------
__global__ void k_transpose(const float* __restrict__ in, __half* __restrict__ out,
                            int R, int C)
{
    __shared__ float t[32][33];
    int c0 = blockIdx.x * 32, r0 = blockIdx.y * 32;
    int x = threadIdx.x, y0 = threadIdx.y;
#pragma unroll
    for (int dy = 0; dy < 32; dy += 8)
        t[y0 + dy][x] = in[(r0 + y0 + dy) * C + c0 + x];
    __syncthreads();
#pragma unroll
    for (int dy = 0; dy < 32; dy += 8)
        out[(c0 + y0 + dy) * R + r0 + x] = __float2half_rn(t[x][y0 + dy]);
}

// ===========================================================================
// tc_gemm_f16 (round-12 proven): fp16 m16n8k16 GEMM, cp.async 3-stage ring.
// OUT16=1 -> fp16 output (chained GEMM), OUT16=0 -> fp32 output.
// ===========================================================================
#define TCH_ST 36
#define TCH_TILE (128 * TCH_ST)
#define TCH_SMEM (3 * 2 * TCH_TILE * 4)

template <int OUT16>
__global__ __launch_bounds__(256, 2)
void tc_gemm_f16(const __half* __restrict__ Am, const __half* __restrict__ Bt,
                 const float* __restrict__ bias, void* __restrict__ Cout,
                 int Nn, int Kk)
{
    extern __shared__ uint32_t smw[];
    uint32_t sbase = smem_u32(smw);

    int tid = threadIdx.x;
    int lane = tid & 31, warp = tid >> 5;
    int wm = warp & 3, wn = warp >> 2;
    int g = lane >> 2, tg = lane & 3;
    int mb = blockIdx.y * 128, nb = blockIdx.x * 128;

    int lr = tid >> 1;
    int lhh = (tid & 1) * 32;
    int lhw = (tid & 1) * 16;

    const __half* Ap = Am + (size_t)(mb + lr) * Kk + lhh;
    const __half* Bp = Bt + (size_t)(nb + lr) * Kk + lhh;
    uint32_t stg_off = (uint32_t)(lr * TCH_ST + lhw) * 4;

    float acc[2][8][4];
#pragma unroll
    for (int mi = 0; mi < 2; mi++)
#pragma unroll
        for (int ni = 0; ni < 8; ni++)
#pragma unroll
            for (int q = 0; q < 4; q++) acc[mi][ni][q] = 0.f;

    int NC = Kk >> 6;

#pragma unroll
    for (int p = 0; p < 2; p++) {
        uint32_t da = sbase + (uint32_t)(p * 2 * TCH_TILE) * 4 + stg_off;
        uint32_t db = da + (uint32_t)TCH_TILE * 4;
        const __half* sa = Ap + p * 64;
        const __half* sb = Bp + p * 64;
#pragma unroll
        for (int i = 0; i < 4; i++) {
            cp16(da + i * 16, sa + i * 8);
            cp16(db + i * 16, sb + i * 8);
        }
        asm volatile("cp.async.commit_group;" ::: "memory");
    }

    for (int s = 0; s < NC; s++) {
        asm volatile("cp.async.wait_group 1;" ::: "memory");
        __syncthreads();

        int p2 = s + 2;
        if (p2 < NC) {
            int nbuf = p2 - (p2 / 3) * 3;
            uint32_t da = sbase + (uint32_t)(nbuf * 2 * TCH_TILE) * 4 + stg_off;
            uint32_t db = da + (uint32_t)TCH_TILE * 4;
            const __half* sa = Ap + p2 * 64;
            const __half* sb = Bp + p2 * 64;
#pragma unroll
            for (int i = 0; i < 4; i++) {
                cp16(da + i * 16, sa + i * 8);
                cp16(db + i * 16, sb + i * 8);
            }
        }
        asm volatile("cp.async.commit_group;" ::: "memory");

        int buf = s - (s / 3) * 3;
        const uint32_t* Ab = smw + buf * 2 * TCH_TILE;
        const uint32_t* Bb = Ab + TCH_TILE;
#pragma unroll
        for (int k16 = 0; k16 < 4; k16++) {
            int k0 = k16 * 8;
            uint32_t af[2][4], bf[8][2];
#pragma unroll
            for (int mi = 0; mi < 2; mi++) {
                int r = wm * 32 + mi * 16 + g;
                af[mi][0] = Ab[r * TCH_ST + k0 + tg];
                af[mi][1] = Ab[(r + 8) * TCH_ST + k0 + tg];
                af[mi][2] = Ab[r * TCH_ST + k0 + tg + 4];
                af[mi][3] = Ab[(r + 8) * TCH_ST + k0 + tg + 4];
            }
#pragma unroll
            for (int ni = 0; ni < 8; ni++) {
                int n = wn * 64 + ni * 8 + g;
                bf[ni][0] = Bb[n * TCH_ST + k0 + tg];
                bf[ni][1] = Bb[n * TCH_ST + k0 + tg + 4];
            }
#pragma unroll
            for (int mi = 0; mi < 2; mi++)
#pragma unroll
                for (int ni = 0; ni < 8; ni++)
                    mma_f16(acc[mi][ni], af[mi], bf[ni]);
        }
    }

#pragma unroll
    for (int mi = 0; mi < 2; mi++) {
        int row = mb + wm * 32 + mi * 16 + g;
#pragma unroll
        for (int ni = 0; ni < 8; ni++) {
            int col = nb + wn * 64 + ni * 8 + tg * 2;
            float b0 = __ldg(bias + col), b1 = __ldg(bias + col + 1);
            float v0 = fmaxf(acc[mi][ni][0] + b0, 0.f);
            float v1 = fmaxf(acc[mi][ni][1] + b1, 0.f);
            float v2 = fmaxf(acc[mi][ni][2] + b0, 0.f);
            float v3 = fmaxf(acc[mi][ni][3] + b1, 0.f);
            if (OUT16) {
                __half* Cm = (__half*)Cout;
                __half2 h01 = __floats2half2_rn(v0, v1);
                __half2 h23 = __floats2half2_rn(v2, v3);
                *(__half2*)(Cm + (size_t)row * Nn + col) = h01;
                *(__half2*)(Cm + (size_t)(row + 8) * Nn + col) = h23;
            } else {
                float* Cm = (float*)Cout;
                *(float2*)(Cm + (size_t)row * Nn + col) = make_float2(v0, v1);
                *(float2*)(Cm + (size_t)(row + 8) * Nn + col) = make_float2(v2, v3);
            }
        }
    }
}

// ---------------------------------------------------------------------------
// Decoder layer 3: recons = tanh(d2 @ Wd3 + bd3). Warp per row; fp32 d2
// (precision-critical), Wd3 staged in smem. Order identical to proven ver.
// ---------------------------------------------------------------------------
__global__ void k_dec3(const float* __restrict__ d2, const float* __restrict__ Wd3,
                       const float* __restrict__ bd3, float* __restrict__ out)
{
    __shared__ float ws[HDIM * ADIM];    // 24KB
    int tid = threadIdx.x;
    for (int e = tid; e < HDIM * ADIM; e += 256)
        ws[e] = Wd3[e];
    __syncthreads();

    int warp = (blockIdx.x * 256 + tid) >> 5;
    int lane = tid & 31;
    const float* row = d2 + (size_t)warp * HDIM;
    float a0 = 0.f, a1 = 0.f, a2 = 0.f, a3 = 0.f, a4 = 0.f, a5 = 0.f;
#pragma unroll 4
    for (int k = lane; k < HDIM; k += 32) {
        float v = row[k];
        const float* w = ws + k * ADIM;
        a0 += v * w[0]; a1 += v * w[1]; a2 += v * w[2];
        a3 += v * w[3]; a4 += v * w[4]; a5 += v * w[5];
    }
#pragma unroll
    for (int off = 16; off; off >>= 1) {
        a0 += __shfl_xor_sync(0xffffffffu, a0, off);
        a1 += __shfl_xor_sync(0xffffffffu, a1, off);
        a2 += __shfl_xor_sync(0xffffffffu, a2, off);
        a3 += __shfl_xor_sync(0xffffffffu, a3, off);
        a4 += __shfl_xor_sync(0xffffffffu, a4, off);
        a5 += __shfl_xor_sync(0xffffffffu, a5, off);
    }
    if (lane == 0) {
        float* o = out + OUT_REC + (size_t)warp * ADIM;
        o[0] = tanhf(a0 + bd3[0]);
        o[1] = tanhf(a1 + bd3[1]);
        o[2] = tanhf(a2 + bd3[2]);
        o[3] = tanhf(a3 + bd3[3]);
        o[4] = tanhf(a4 + bd3[4]);
        o[5] = tanhf(a5 + bd3[5]);
    }
}

// ---------------------------------------------------------------------------
// Final loss reduction (4096 partials)
// ---------------------------------------------------------------------------
__global__ void k_loss(const float* __restrict__ part, float* __restrict__ out)
{
    __shared__ float s[256];
    int tid = threadIdx.x;
    float a = 0.f;
    for (int i = 0; i < 16; i++) a += part[tid + 256 * i];
    s[tid] = a;
    __syncthreads();
    for (int st = 128; st > 0; st >>= 1) {
        if (tid < st) s[tid] += s[tid + st];
        __syncthreads();
    }
    if (tid == 0)
        out[OUT_LOSS] = 1.25f * s[0] / (float)(NTOK * DDIM);
}

// ---------------------------------------------------------------------------
extern "C" void kernel_launch(void* const* d_in, const int* in_sizes, int n_in,
                              void* d_out, int out_size)
{
    const float* action = (const float*)d_in[0];
    const float* W1   = (const float*)d_in[1];
    const float* b1   = (const float*)d_in[2];
    const float* W2   = (const float*)d_in[3];
    const float* b2   = (const float*)d_in[4];
    const float* Wmu  = (const float*)d_in[5];
    const float* bmu  = (const float*)d_in[6];
    const float* cb   = (const float*)d_in[7];
    const float* Wd1  = (const float*)d_in[8];
    const float* bd1  = (const float*)d_in[9];
    const float* Wd2  = (const float*)d_in[10];
    const float* bd2  = (const float*)d_in[11];
    const float* Wd3  = (const float*)d_in[12];
    const float* bd3  = (const float*)d_in[13];
    float* out = (float*)d_out;

    float *p_h1, *p_h2, *p_lat, *p_ln, *p_cn, *p_part;
    __half *p_cbh, *p_h1h, *p_qh, *p_wt1, *p_wt2;
    unsigned short* p_cand;
    int* p_ccnt;
    cudaGetSymbolAddress((void**)&p_h1, g_h1);
    cudaGetSymbolAddress((void**)&p_h2, g_h2);
    cudaGetSymbolAddress((void**)&p_h1h, g_h1h);
    cudaGetSymbolAddress((void**)&p_lat, g_lat);
    cudaGetSymbolAddress((void**)&p_qh, g_qh);
    cudaGetSymbolAddress((void**)&p_ln, g_ln);
    cudaGetSymbolAddress((void**)&p_cn, g_cn);
    cudaGetSymbolAddress((void**)&p_cbh, g_cbh);
    cudaGetSymbolAddress((void**)&p_part, g_part);
    cudaGetSymbolAddress((void**)&p_wt1, g_wt1);
    cudaGetSymbolAddress((void**)&p_wt2, g_wt2);
    cudaGetSymbolAddress((void**)&p_cand, g_cand);
    cudaGetSymbolAddress((void**)&p_ccnt, g_ccnt);

    cudaFuncSetAttribute(tc_gemm_f16<1>, cudaFuncAttributeMaxDynamicSharedMemorySize,
                         TCH_SMEM);
    cudaFuncSetAttribute(tc_gemm_f16<0>, cudaFuncAttributeMaxDynamicSharedMemorySize,
                         TCH_SMEM);
    cudaFuncSetAttribute(k_vq_screen, cudaFuncAttributeMaxDynamicSharedMemorySize,
                         SCH_SMEM);

    // ---- fork: independent prep kernels on a side stream (graph branch) ----
    cudaStream_t s2;
    cudaEvent_t ev_fork, ev_join;
    cudaStreamCreateWithFlags(&s2, cudaStreamNonBlocking);
    cudaEventCreateWithFlags(&ev_fork, cudaEventDisableTiming);
    cudaEventCreateWithFlags(&ev_join, cudaEventDisableTiming);
    cudaEventRecord(ev_fork, 0);
    cudaStreamWaitEvent(s2, ev_fork, 0);

    k_transpose<<<dim3(HDIM / 32, DDIM / 32), dim3(32, 8), 0, s2>>>(Wd1, p_wt1, DDIM, HDIM);
    k_transpose<<<dim3(HDIM / 32, HDIM / 32), dim3(32, 8), 0, s2>>>(Wd2, p_wt2, HDIM, HDIM);
    k_cnorm<<<KCB / 8, 256, 0, s2>>>(cb, p_cn, p_cbh);
    cudaEventRecord(ev_join, s2);

    // ---- main stream: encoder (fp32-exact — argmin-critical) ----
    k_enc1<<<(NTOK * HDIM) / 1024, 256>>>(action, W1, b1, p_h1);
    sgemm<1><<<dim3(HDIM / 128, NTOK / 128), 256>>>(p_h1, W2, b2, p_h2, NTOK, HDIM, HDIM);
    sgemm<0><<<dim3(DDIM / 128, NTOK / 128), 256>>>(p_h2, Wmu, bmu, p_lat, NTOK, DDIM, HDIM);
    k_rownorm<<<NTOK / 8, 256>>>(p_lat, p_ln);

    // join the prep branch before VQ (screen needs cbh/cn; decoder needs wt1/wt2)
    cudaStreamWaitEvent(0, ev_join, 0);

    // vector quantization: fp16 tensor screening + tiny exact verify
    k_vq_screen<<<NTOK / 64, 256, SCH_SMEM>>>(p_lat, p_cbh, p_cn, p_cand, p_ccnt);
    k_vq_exact<<<VQ2_BLOCKS, 256>>>(p_lat, cb, p_cn, p_ln, p_cand, p_ccnt,
                                    out, p_qh, p_part);

    // decoder (fp16 tensor-core; h2 fp32 — precision-critical for output 2)
    tc_gemm_f16<1><<<dim3(HDIM / 128, NTOK / 128), 256, TCH_SMEM>>>(p_qh, p_wt1, bd1, p_h1h, HDIM, DDIM);
    tc_gemm_f16<0><<<dim3(HDIM / 128, NTOK / 128), 256, TCH_SMEM>>>(p_h1h, p_wt2, bd2, p_h2, HDIM, HDIM);
    k_dec3<<<NTOK / 8, 256>>>(p_h2, Wd3, bd3, out);

    // scalar loss
    k_loss<<<1, 256>>>(p_part, out);
}

// round 16
// speedup vs baseline: 1.0114x; 1.0049x over previous
#include <cuda_runtime.h>
#include <cuda_fp16.h>
#include <math.h>
#include <stdint.h>

// Problem dims
#define NTOK 32768
#define ADIM 6
#define HDIM 1024
#define DDIM 128
#define KCB  4096

// Output layout (float32, concatenated in reference-return order)
#define OUT_INDS 0
#define OUT_Q    (NTOK)
#define OUT_REC  (NTOK + NTOK * DDIM)
#define OUT_LOSS (NTOK + NTOK * DDIM + NTOK * ADIM)

#define CAPS 64
#define TAU 8e-6f
#define VQ2_BLOCKS (NTOK / 8)   // 4096

// -------- scratch (device globals; no runtime allocation) --------
__device__ float g_h1[NTOK * HDIM];
__device__ float g_h2[NTOK * HDIM];    // fp32 h2 (precision-critical for out2)
__device__ __half g_h1h[NTOK * HDIM];  // fp16 h1 (decoder intermediate)
__device__ float g_lat[NTOK * DDIM];
__device__ __half g_qh[NTOK * DDIM];   // fp16 quantized_st (decoder input)
__device__ float g_cn[KCB];
__device__ __half g_cbh[KCB * DDIM];   // fp16 codebook (screen only)
__device__ float g_part[VQ2_BLOCKS];
__device__ __half g_wt1[HDIM * DDIM];  // Wd1^T fp16
__device__ __half g_wt2[HDIM * HDIM];  // Wd2^T fp16
__device__ unsigned short g_cand[NTOK * CAPS];
__device__ int g_ccnt[NTOK];

__device__ __forceinline__ uint32_t smem_u32(const void* p)
{
    uint32_t a;
    asm("{ .reg .u64 t; cvta.to.shared.u64 t, %1; cvt.u32.u64 %0, t; }"
        : "=r"(a) : "l"(p));
    return a;
}
__device__ __forceinline__ void cp16(uint32_t dst, const void* src)
{
    asm volatile("cp.async.cg.shared.global [%0], [%1], 16;"
                 :: "r"(dst), "l"(src) : "memory");
}
__device__ __forceinline__ void mma_f16(float* c, const uint32_t* a, const uint32_t* b)
{
    asm("mma.sync.aligned.m16n8k16.row.col.f32.f16.f16.f32 "
        "{%0,%1,%2,%3}, {%4,%5,%6,%7}, {%8,%9}, {%0,%1,%2,%3};"
        : "+f"(c[0]), "+f"(c[1]), "+f"(c[2]), "+f"(c[3])
        : "r"(a[0]), "r"(a[1]), "r"(a[2]), "r"(a[3]), "r"(b[0]), "r"(b[1]));
}

// ---------------------------------------------------------------------------
// Codebook norms + fp16 codebook (XLA-order reduction, argmin-tie critical)
// ---------------------------------------------------------------------------
__global__ void k_cnorm(const float* __restrict__ cb, float* __restrict__ cn,
                        __half* __restrict__ cbh)
{
    int w = (blockIdx.x * blockDim.x + threadIdx.x) >> 5;
    int lane = threadIdx.x & 31;
    const float* row = cb + w * DDIM;
    __half* hrow = cbh + (size_t)w * DDIM;
    float acc = 0.f;
#pragma unroll
    for (int i = 0; i < 4; i++) {
        float v = row[lane + i * 32];
        hrow[lane + i * 32] = __float2half_rn(v);
        acc = __fadd_rn(acc, __fmul_rn(v, v));
    }
#pragma unroll
    for (int off = 16; off >= 1; off >>= 1)
        acc = __fadd_rn(acc, __shfl_down_sync(0xffffffffu, acc, off));
    if (lane == 0) cn[w] = acc;
}

// ---------------------------------------------------------------------------
// Encoder layer 1 (A=6), 4 outputs/thread (round-11 proven)
// ---------------------------------------------------------------------------
__global__ void k_enc1(const float* __restrict__ act, const float* __restrict__ W1,
                       const float* __restrict__ b1, float* __restrict__ h1)
{
    int gid = blockIdx.x * blockDim.x + threadIdx.x;
    int n = gid >> 8;
    int h = (gid & 255) * 4;
    const float* a = act + n * ADIM;
    float av[ADIM];
#pragma unroll
    for (int k = 0; k < ADIM; k++) av[k] = a[k];
    float4 s = make_float4(0.f, 0.f, 0.f, 0.f);
#pragma unroll
    for (int k = 0; k < ADIM; k++) {
        float4 w = *(const float4*)(W1 + k * HDIM + h);
        s.x = __fmaf_rn(av[k], w.x, s.x);
        s.y = __fmaf_rn(av[k], w.y, s.y);
        s.z = __fmaf_rn(av[k], w.z, s.z);
        s.w = __fmaf_rn(av[k], w.w, s.w);
    }
    float4 b = *(const float4*)(b1 + h);
    s.x = fmaxf(__fadd_rn(s.x, b.x), 0.f);
    s.y = fmaxf(__fadd_rn(s.y, b.y), 0.f);
    s.z = fmaxf(__fadd_rn(s.z, b.z), 0.f);
    s.w = fmaxf(__fadd_rn(s.w, b.w), 0.f);
    *(float4*)(h1 + (size_t)n * HDIM + h) = s;
}

// ---------------------------------------------------------------------------
// FP32 SGEMM (round-3 proven) — ENCODER ONLY (argmin-critical path)
// ---------------------------------------------------------------------------
template <int RELU>
__global__ __launch_bounds__(256)
void sgemm(const float* __restrict__ Am, const float* __restrict__ Bm,
           const float* __restrict__ bias, float* __restrict__ Cm,
           int M, int Nn, int Kk)
{
    __shared__ float As[8][128];
    __shared__ float Bs[8][128];

    int tid = threadIdx.x;
    int tx = tid & 15;
    int ty = tid >> 4;
    int mb = blockIdx.y * 128;
    int nb = blockIdx.x * 128;

    int arow = tid >> 1;
    int acol = (tid & 1) * 4;
    int brow = tid >> 5;
    int bcol = (tid & 31) * 4;

    const float* Aptr = Am + (mb + arow) * Kk + acol;
    const float* Bptr = Bm + brow * Nn + nb + bcol;

    float acc[8][8];
#pragma unroll
    for (int i = 0; i < 8; i++)
#pragma unroll
        for (int j = 0; j < 8; j++) acc[i][j] = 0.f;

    for (int k0 = 0; k0 < Kk; k0 += 8) {
        float4 av = *(const float4*)Aptr;
        As[acol + 0][arow] = av.x;
        As[acol + 1][arow] = av.y;
        As[acol + 2][arow] = av.z;
        As[acol + 3][arow] = av.w;
        *(float4*)&Bs[brow][bcol] = *(const float4*)Bptr;
        __syncthreads();

#pragma unroll
        for (int kk = 0; kk < 8; kk++) {
            float4 a0 = *(const float4*)&As[kk][ty * 8];
            float4 a1 = *(const float4*)&As[kk][ty * 8 + 4];
            float4 b0 = *(const float4*)&Bs[kk][tx * 8];
            float4 b1 = *(const float4*)&Bs[kk][tx * 8 + 4];
            float av8[8] = {a0.x, a0.y, a0.z, a0.w, a1.x, a1.y, a1.z, a1.w};
            float bv8[8] = {b0.x, b0.y, b0.z, b0.w, b1.x, b1.y, b1.z, b1.w};
#pragma unroll
            for (int i = 0; i < 8; i++)
#pragma unroll
                for (int j = 0; j < 8; j++)
                    acc[i][j] = __fmaf_rn(av8[i], bv8[j], acc[i][j]);
        }
        __syncthreads();
        Aptr += 8;
        Bptr += 8 * Nn;
    }

#pragma unroll
    for (int i = 0; i < 8; i++) {
        int row = mb + ty * 8 + i;
        float* Crow = Cm + row * Nn + nb + tx * 8;
        const float* brow2 = bias + nb + tx * 8;
#pragma unroll
        for (int j = 0; j < 8; j++) {
            float v = __fadd_rn(acc[i][j], brow2[j]);
            if (RELU) v = fmaxf(v, 0.f);
            Crow[j] = v;
        }
    }
}

// ===========================================================================
// VQ stage A: fp16 m16n8k16 tensor screening (round-11 proven, verbatim)
// ===========================================================================
#define SCH_ST 68
#define SCH_LAT (64 * SCH_ST)
#define SCH_CB  (32 * SCH_ST)
#define SCH_SMEM ((SCH_LAT + 3 * SCH_CB) * 4)

__global__ __launch_bounds__(256, 2)
void k_vq_screen(const float* __restrict__ lat, const __half* __restrict__ cbh,
                 const float* __restrict__ cn,
                 unsigned short* __restrict__ cand, int* __restrict__ ccnt)
{
    extern __shared__ uint32_t smh[];
    uint32_t* Lw = smh;
    uint32_t* Cw = smh + SCH_LAT;
    __shared__ unsigned short s_cand[64 * CAPS];
    __shared__ float s_dv[64 * CAPS];
    __shared__ float s_minw[64][2];
    __shared__ int s_cnt[64];

    int tid = threadIdx.x;
    int lane = tid & 31, warp = tid >> 5;
    int wm = warp & 3, wn = warp >> 2;
    int g = lane >> 2, tg = lane & 3;
    int m0 = blockIdx.x * 64;

    if (tid < 64) s_cnt[tid] = 0;

    {
        int r = tid >> 2;
        int c0w = (tid & 3) * 16;
        const float4* src = (const float4*)(lat + (size_t)(m0 + r) * DDIM + (tid & 3) * 32);
        uint32_t* dst = Lw + r * SCH_ST + c0w;
#pragma unroll
        for (int i = 0; i < 8; i++) {
            float4 v = src[i];
            __half2 h0 = __floats2half2_rn(v.x, v.y);
            __half2 h1 = __floats2half2_rn(v.z, v.w);
            dst[i * 2] = *(uint32_t*)&h0;
            dst[i * 2 + 1] = *(uint32_t*)&h1;
        }
    }

    uint32_t sb = smem_u32(Cw);
    int cr = tid >> 3;
    int ck = tid & 7;

#pragma unroll
    for (int p = 0; p < 2; p++) {
        const __half* src = cbh + (size_t)(p * 32 + cr) * DDIM;
        uint32_t d = sb + (uint32_t)(p * SCH_CB + cr * SCH_ST) * 4;
        cp16(d + ck * 16, src + ck * 8);
        cp16(d + (ck + 8) * 16, src + (ck + 8) * 8);
        asm volatile("cp.async.commit_group;" ::: "memory");
    }

    float rmin0 = 3.4e38f, rmin1 = 3.4e38f;
    int r0 = wm * 16 + g, r1 = r0 + 8;
    const uint32_t* Ar0 = Lw + r0 * SCH_ST;
    const uint32_t* Ar1 = Lw + r1 * SCH_ST;

    for (int ch = 0; ch < 128; ch++) {
        asm volatile("cp.async.wait_group 1;" ::: "memory");
        __syncthreads();

        int p2 = ch + 2;
        if (p2 < 128) {
            int nbuf = p2 - (p2 / 3) * 3;
            const __half* src = cbh + (size_t)(p2 * 32 + cr) * DDIM;
            uint32_t d = sb + (uint32_t)(nbuf * SCH_CB + cr * SCH_ST) * 4;
            cp16(d + ck * 16, src + ck * 8);
            cp16(d + (ck + 8) * 16, src + (ck + 8) * 8);
        }
        asm volatile("cp.async.commit_group;" ::: "memory");

        int buf = ch - (ch / 3) * 3;
        const uint32_t* Cb = Cw + buf * SCH_CB;

        float acc[2][4];
#pragma unroll
        for (int ni = 0; ni < 2; ni++)
#pragma unroll
            for (int q = 0; q < 4; q++) acc[ni][q] = 0.f;

#pragma unroll
        for (int k8 = 0; k8 < 8; k8++) {
            int k0 = k8 * 8;
            uint32_t af[4];
            af[0] = Ar0[k0 + tg];
            af[1] = Ar1[k0 + tg];
            af[2] = Ar0[k0 + tg + 4];
            af[3] = Ar1[k0 + tg + 4];
#pragma unroll
            for (int ni = 0; ni < 2; ni++) {
                const uint32_t* Br = Cb + (wn * 16 + ni * 8 + g) * SCH_ST + k0;
                uint32_t bf[2] = {Br[tg], Br[tg + 4]};
                mma_f16(acc[ni], af, bf);
            }
        }

        float dv[2][4];
        int cbase[2];
        float dmin0 = 3.4e38f, dmin1 = 3.4e38f;
#pragma unroll
        for (int ni = 0; ni < 2; ni++) {
            int code0 = ch * 32 + wn * 16 + ni * 8 + tg * 2;
            float c0v = __ldg(cn + code0);
            float c1v = __ldg(cn + code0 + 1);
            dv[ni][0] = c0v - 2.f * acc[ni][0];
            dv[ni][1] = c1v - 2.f * acc[ni][1];
            dv[ni][2] = c0v - 2.f * acc[ni][2];
            dv[ni][3] = c1v - 2.f * acc[ni][3];
            cbase[ni] = code0;
            dmin0 = fminf(dmin0, fminf(dv[ni][0], dv[ni][1]));
            dmin1 = fminf(dmin1, fminf(dv[ni][2], dv[ni][3]));
        }
        dmin0 = fminf(dmin0, __shfl_xor_sync(0xffffffffu, dmin0, 1));
        dmin0 = fminf(dmin0, __shfl_xor_sync(0xffffffffu, dmin0, 2));
        dmin1 = fminf(dmin1, __shfl_xor_sync(0xffffffffu, dmin1, 1));
        dmin1 = fminf(dmin1, __shfl_xor_sync(0xffffffffu, dmin1, 2));
        rmin0 = fminf(rmin0, dmin0);
        rmin1 = fminf(rmin1, dmin1);
        float th0 = rmin0 + TAU, th1 = rmin1 + TAU;

#pragma unroll
        for (int ni = 0; ni < 2; ni++) {
#pragma unroll
            for (int h = 0; h < 2; h++) {
                float d0 = dv[ni][h];
                if (d0 <= th0) {
                    int s_ = atomicAdd(&s_cnt[r0], 1);
                    if (s_ < CAPS) {
                        s_cand[r0 * CAPS + s_] = (unsigned short)(cbase[ni] + h);
                        s_dv[r0 * CAPS + s_] = d0;
                    }
                }
                float d1 = dv[ni][h + 2];
                if (d1 <= th1) {
                    int s_ = atomicAdd(&s_cnt[r1], 1);
                    if (s_ < CAPS) {
                        s_cand[r1 * CAPS + s_] = (unsigned short)(cbase[ni] + h);
                        s_dv[r1 * CAPS + s_] = d1;
                    }
                }
            }
        }
    }

    __syncthreads();
    if (tg == 0) {
        s_minw[r0][wn] = rmin0;
        s_minw[r1][wn] = rmin1;
    }
    __syncthreads();

    if (tid < 64) {
        int r = tid;
        int n = s_cnt[r];
        if (n > CAPS) {
            ccnt[m0 + r] = n;
        } else {
            float th = fminf(s_minw[r][0], s_minw[r][1]) + TAU;
            int k = 0;
            for (int i = 0; i < n; i++) {
                if (s_dv[r * CAPS + i] <= th) {
                    s_cand[r * CAPS + k] = s_cand[r * CAPS + i];
                    k++;
                }
            }
            ccnt[m0 + r] = k;
        }
    }
    __syncthreads();

    for (int e = tid; e < 64 * CAPS; e += 256)
        cand[(size_t)m0 * CAPS + e] = s_cand[e];
}

// ===========================================================================
// VQ stage B: exact verification (round-9 proven) + fused row-norm.
// Lr computed in-warp with the EXACT XLA reduction order (lane-strided
// squares, shfl_down 16..1) on the staged latent row -> bit-identical to
// the previous k_rownorm output.
// ===========================================================================
__global__ __launch_bounds__(256)
void k_vq_exact(const float* __restrict__ lat, const float* __restrict__ cb,
                const float* __restrict__ cn,
                const unsigned short* __restrict__ cand,
                const int* __restrict__ ccnt,
                float* __restrict__ out, __half* __restrict__ gq,
                float* __restrict__ part)
{
    __shared__ float s_lat[8][128];
    __shared__ float s_part[8];
    int tid = threadIdx.x, lane = tid & 31, w = tid >> 5;
    int r = blockIdx.x * 8 + w;

    ((float4*)s_lat[w])[lane] = ((const float4*)(lat + (size_t)r * DDIM))[lane];
    __syncwarp();

    const float* lrow = s_lat[w];

    // fused row norm: XLA-order (lane-strided squares, shfl_down tree)
    float Lr;
    {
        float nacc = 0.f;
#pragma unroll
        for (int i = 0; i < 4; i++) {
            float v = lrow[lane + i * 32];
            nacc = __fadd_rn(nacc, __fmul_rn(v, v));
        }
#pragma unroll
        for (int off = 16; off >= 1; off >>= 1)
            nacc = __fadd_rn(nacc, __shfl_down_sync(0xffffffffu, nacc, off));
        Lr = __shfl_sync(0xffffffffu, nacc, 0);
    }

    int cnt = ccnt[r];

    float bestv = 3.4e38f;
    int besti = 0x7FFFFFFF;

    if (cnt <= CAPS) {
        if (lane < cnt) {
            int code = cand[(size_t)r * CAPS + lane];
            const float4* c4 = (const float4*)(cb + (size_t)code * DDIM);
            float acc = 0.f;
#pragma unroll
            for (int i = 0; i < 32; i++) {
                float4 c = __ldg(c4 + i);
                acc = __fmaf_rn(lrow[i * 4 + 0], c.x, acc);
                acc = __fmaf_rn(lrow[i * 4 + 1], c.y, acc);
                acc = __fmaf_rn(lrow[i * 4 + 2], c.z, acc);
                acc = __fmaf_rn(lrow[i * 4 + 3], c.w, acc);
            }
            bestv = __fsub_rn(__fadd_rn(Lr, __ldg(cn + code)),
                              __fmul_rn(2.f, acc));
            besti = code;
        }
    } else {
        for (int c0 = lane; c0 < KCB; c0 += 32) {
            const float4* c4 = (const float4*)(cb + (size_t)c0 * DDIM);
            float acc = 0.f;
#pragma unroll 8
            for (int i = 0; i < 32; i++) {
                float4 c = __ldg(c4 + i);
                acc = __fmaf_rn(lrow[i * 4 + 0], c.x, acc);
                acc = __fmaf_rn(lrow[i * 4 + 1], c.y, acc);
                acc = __fmaf_rn(lrow[i * 4 + 2], c.z, acc);
                acc = __fmaf_rn(lrow[i * 4 + 3], c.w, acc);
            }
            float dist = __fsub_rn(__fadd_rn(Lr, __ldg(cn + c0)),
                                   __fmul_rn(2.f, acc));
            if (dist < bestv || (dist == bestv && c0 < besti)) {
                bestv = dist; besti = c0;
            }
        }
    }

#pragma unroll
    for (int o = 16; o >= 1; o >>= 1) {
        float ov = __shfl_xor_sync(0xffffffffu, bestv, o);
        int oi = __shfl_xor_sync(0xffffffffu, besti, o);
        if (ov < bestv || (ov == bestv && oi < besti)) { bestv = ov; besti = oi; }
    }

    if (lane == 0) out[OUT_INDS + r] = (float)besti;

    const float* qrow = cb + (size_t)besti * DDIM;
    float lsum = 0.f;
#pragma unroll
    for (int i = 0; i < 4; i++) {
        int d = lane + i * 32;
        float l = lrow[d], q = qrow[d];
        float qmL = q - l;
        float qst = l + qmL;
        out[OUT_Q + (size_t)r * DDIM + d] = qst;
        gq[(size_t)r * DDIM + d] = __float2half_rn(qst);
        lsum += qmL * qmL;
    }
#pragma unroll
    for (int o = 16; o >= 1; o >>= 1)
        lsum += __shfl_xor_sync(0xffffffffu, lsum, o);
    if (lane == 0) s_part[w] = lsum;
    __syncthreads();
    if (tid == 0) {
        float s = 0.f;
        for (int i = 0; i < 8; i++) s += s_part[i];
        part[blockIdx.x] = s;
    }
}

// ---------------------------------------------------------------------------
// Weight transpose + fp16 convert: out[c][r] = fp16(in[r][c])
// ---------------------------------------------------------------------------
__global__ void k_transpose(const float* __restrict__ in, __half* __restrict__ out,
                            int R, int C)
{
    __shared__ float t[32][33];
    int c0 = blockIdx.x * 32, r0 = blockIdx.y * 32;
    int x = threadIdx.x, y0 = threadIdx.y;
#pragma unroll
    for (int dy = 0; dy < 32; dy += 8)
        t[y0 + dy][x] = in[(r0 + y0 + dy) * C + c0 + x];
    __syncthreads();
#pragma unroll
    for (int dy = 0; dy < 32; dy += 8)
        out[(c0 + y0 + dy) * R + r0 + x] = __float2half_rn(t[x][y0 + dy]);
}

// ===========================================================================
// tc_gemm_f16 (round-12 proven): fp16 m16n8k16 GEMM, cp.async 3-stage ring.
// OUT16=1 -> fp16 output (chained GEMM), OUT16=0 -> fp32 output.
// ===========================================================================
#define TCH_ST 36
#define TCH_TILE (128 * TCH_ST)
#define TCH_SMEM (3 * 2 * TCH_TILE * 4)

template <int OUT16>
__global__ __launch_bounds__(256, 2)
void tc_gemm_f16(const __half* __restrict__ Am, const __half* __restrict__ Bt,
                 const float* __restrict__ bias, void* __restrict__ Cout,
                 int Nn, int Kk)
{
    extern __shared__ uint32_t smw[];
    uint32_t sbase = smem_u32(smw);

    int tid = threadIdx.x;
    int lane = tid & 31, warp = tid >> 5;
    int wm = warp & 3, wn = warp >> 2;
    int g = lane >> 2, tg = lane & 3;
    int mb = blockIdx.y * 128, nb = blockIdx.x * 128;

    int lr = tid >> 1;
    int lhh = (tid & 1) * 32;
    int lhw = (tid & 1) * 16;

    const __half* Ap = Am + (size_t)(mb + lr) * Kk + lhh;
    const __half* Bp = Bt + (size_t)(nb + lr) * Kk + lhh;
    uint32_t stg_off = (uint32_t)(lr * TCH_ST + lhw) * 4;

    float acc[2][8][4];
#pragma unroll
    for (int mi = 0; mi < 2; mi++)
#pragma unroll
        for (int ni = 0; ni < 8; ni++)
#pragma unroll
            for (int q = 0; q < 4; q++) acc[mi][ni][q] = 0.f;

    int NC = Kk >> 6;

#pragma unroll
    for (int p = 0; p < 2; p++) {
        uint32_t da = sbase + (uint32_t)(p * 2 * TCH_TILE) * 4 + stg_off;
        uint32_t db = da + (uint32_t)TCH_TILE * 4;
        const __half* sa = Ap + p * 64;
        const __half* sb = Bp + p * 64;
#pragma unroll
        for (int i = 0; i < 4; i++) {
            cp16(da + i * 16, sa + i * 8);
            cp16(db + i * 16, sb + i * 8);
        }
        asm volatile("cp.async.commit_group;" ::: "memory");
    }

    for (int s = 0; s < NC; s++) {
        asm volatile("cp.async.wait_group 1;" ::: "memory");
        __syncthreads();

        int p2 = s + 2;
        if (p2 < NC) {
            int nbuf = p2 - (p2 / 3) * 3;
            uint32_t da = sbase + (uint32_t)(nbuf * 2 * TCH_TILE) * 4 + stg_off;
            uint32_t db = da + (uint32_t)TCH_TILE * 4;
            const __half* sa = Ap + p2 * 64;
            const __half* sb = Bp + p2 * 64;
#pragma unroll
            for (int i = 0; i < 4; i++) {
                cp16(da + i * 16, sa + i * 8);
                cp16(db + i * 16, sb + i * 8);
            }
        }
        asm volatile("cp.async.commit_group;" ::: "memory");

        int buf = s - (s / 3) * 3;
        const uint32_t* Ab = smw + buf * 2 * TCH_TILE;
        const uint32_t* Bb = Ab + TCH_TILE;
#pragma unroll
        for (int k16 = 0; k16 < 4; k16++) {
            int k0 = k16 * 8;
            uint32_t af[2][4], bf[8][2];
#pragma unroll
            for (int mi = 0; mi < 2; mi++) {
                int r = wm * 32 + mi * 16 + g;
                af[mi][0] = Ab[r * TCH_ST + k0 + tg];
                af[mi][1] = Ab[(r + 8) * TCH_ST + k0 + tg];
                af[mi][2] = Ab[r * TCH_ST + k0 + tg + 4];
                af[mi][3] = Ab[(r + 8) * TCH_ST + k0 + tg + 4];
            }
#pragma unroll
            for (int ni = 0; ni < 8; ni++) {
                int n = wn * 64 + ni * 8 + g;
                bf[ni][0] = Bb[n * TCH_ST + k0 + tg];
                bf[ni][1] = Bb[n * TCH_ST + k0 + tg + 4];
            }
#pragma unroll
            for (int mi = 0; mi < 2; mi++)
#pragma unroll
                for (int ni = 0; ni < 8; ni++)
                    mma_f16(acc[mi][ni], af[mi], bf[ni]);
        }
    }

#pragma unroll
    for (int mi = 0; mi < 2; mi++) {
        int row = mb + wm * 32 + mi * 16 + g;
#pragma unroll
        for (int ni = 0; ni < 8; ni++) {
            int col = nb + wn * 64 + ni * 8 + tg * 2;
            float b0 = __ldg(bias + col), b1 = __ldg(bias + col + 1);
            float v0 = fmaxf(acc[mi][ni][0] + b0, 0.f);
            float v1 = fmaxf(acc[mi][ni][1] + b1, 0.f);
            float v2 = fmaxf(acc[mi][ni][2] + b0, 0.f);
            float v3 = fmaxf(acc[mi][ni][3] + b1, 0.f);
            if (OUT16) {
                __half* Cm = (__half*)Cout;
                __half2 h01 = __floats2half2_rn(v0, v1);
                __half2 h23 = __floats2half2_rn(v2, v3);
                *(__half2*)(Cm + (size_t)row * Nn + col) = h01;
                *(__half2*)(Cm + (size_t)(row + 8) * Nn + col) = h23;
            } else {
                float* Cm = (float*)Cout;
                *(float2*)(Cm + (size_t)row * Nn + col) = make_float2(v0, v1);
                *(float2*)(Cm + (size_t)(row + 8) * Nn + col) = make_float2(v2, v3);
            }
        }
    }
}

// ---------------------------------------------------------------------------
// Decoder layer 3: recons = tanh(d2 @ Wd3 + bd3). Warp per row; fp32 d2
// (precision-critical), Wd3 staged in smem.
// ---------------------------------------------------------------------------
__global__ void k_dec3(const float* __restrict__ d2, const float* __restrict__ Wd3,
                       const float* __restrict__ bd3, float* __restrict__ out)
{
    __shared__ float ws[HDIM * ADIM];    // 24KB
    int tid = threadIdx.x;
    for (int e = tid; e < HDIM * ADIM; e += 256)
        ws[e] = Wd3[e];
    __syncthreads();

    int warp = (blockIdx.x * 256 + tid) >> 5;
    int lane = tid & 31;
    const float* row = d2 + (size_t)warp * HDIM;
    float a0 = 0.f, a1 = 0.f, a2 = 0.f, a3 = 0.f, a4 = 0.f, a5 = 0.f;
#pragma unroll 4
    for (int k = lane; k < HDIM; k += 32) {
        float v = row[k];
        const float* w = ws + k * ADIM;
        a0 += v * w[0]; a1 += v * w[1]; a2 += v * w[2];
        a3 += v * w[3]; a4 += v * w[4]; a5 += v * w[5];
    }
#pragma unroll
    for (int off = 16; off; off >>= 1) {
        a0 += __shfl_xor_sync(0xffffffffu, a0, off);
        a1 += __shfl_xor_sync(0xffffffffu, a1, off);
        a2 += __shfl_xor_sync(0xffffffffu, a2, off);
        a3 += __shfl_xor_sync(0xffffffffu, a3, off);
        a4 += __shfl_xor_sync(0xffffffffu, a4, off);
        a5 += __shfl_xor_sync(0xffffffffu, a5, off);
    }
    if (lane == 0) {
        float* o = out + OUT_REC + (size_t)warp * ADIM;
        o[0] = tanhf(a0 + bd3[0]);
        o[1] = tanhf(a1 + bd3[1]);
        o[2] = tanhf(a2 + bd3[2]);
        o[3] = tanhf(a3 + bd3[3]);
        o[4] = tanhf(a4 + bd3[4]);
        o[5] = tanhf(a5 + bd3[5]);
    }
}

// ---------------------------------------------------------------------------
// Final loss reduction (4096 partials)
// ---------------------------------------------------------------------------
__global__ void k_loss(const float* __restrict__ part, float* __restrict__ out)
{
    __shared__ float s[256];
    int tid = threadIdx.x;
    float a = 0.f;
    for (int i = 0; i < 16; i++) a += part[tid + 256 * i];
    s[tid] = a;
    __syncthreads();
    for (int st = 128; st > 0; st >>= 1) {
        if (tid < st) s[tid] += s[tid + st];
        __syncthreads();
    }
    if (tid == 0)
        out[OUT_LOSS] = 1.25f * s[0] / (float)(NTOK * DDIM);
}

// ---------------------------------------------------------------------------
extern "C" void kernel_launch(void* const* d_in, const int* in_sizes, int n_in,
                              void* d_out, int out_size)
{
    const float* action = (const float*)d_in[0];
    const float* W1   = (const float*)d_in[1];
    const float* b1   = (const float*)d_in[2];
    const float* W2   = (const float*)d_in[3];
    const float* b2   = (const float*)d_in[4];
    const float* Wmu  = (const float*)d_in[5];
    const float* bmu  = (const float*)d_in[6];
    const float* cb   = (const float*)d_in[7];
    const float* Wd1  = (const float*)d_in[8];
    const float* bd1  = (const float*)d_in[9];
    const float* Wd2  = (const float*)d_in[10];
    const float* bd2  = (const float*)d_in[11];
    const float* Wd3  = (const float*)d_in[12];
    const float* bd3  = (const float*)d_in[13];
    float* out = (float*)d_out;

    float *p_h1, *p_h2, *p_lat, *p_cn, *p_part;
    __half *p_cbh, *p_h1h, *p_qh, *p_wt1, *p_wt2;
    unsigned short* p_cand;
    int* p_ccnt;
    cudaGetSymbolAddress((void**)&p_h1, g_h1);
    cudaGetSymbolAddress((void**)&p_h2, g_h2);
    cudaGetSymbolAddress((void**)&p_h1h, g_h1h);
    cudaGetSymbolAddress((void**)&p_lat, g_lat);
    cudaGetSymbolAddress((void**)&p_qh, g_qh);
    cudaGetSymbolAddress((void**)&p_cn, g_cn);
    cudaGetSymbolAddress((void**)&p_cbh, g_cbh);
    cudaGetSymbolAddress((void**)&p_part, g_part);
    cudaGetSymbolAddress((void**)&p_wt1, g_wt1);
    cudaGetSymbolAddress((void**)&p_wt2, g_wt2);
    cudaGetSymbolAddress((void**)&p_cand, g_cand);
    cudaGetSymbolAddress((void**)&p_ccnt, g_ccnt);

    cudaFuncSetAttribute(tc_gemm_f16<1>, cudaFuncAttributeMaxDynamicSharedMemorySize,
                         TCH_SMEM);
    cudaFuncSetAttribute(tc_gemm_f16<0>, cudaFuncAttributeMaxDynamicSharedMemorySize,
                         TCH_SMEM);
    cudaFuncSetAttribute(k_vq_screen, cudaFuncAttributeMaxDynamicSharedMemorySize,
                         SCH_SMEM);

    // ---- fork: independent prep kernels on a side stream (graph branch) ----
    cudaStream_t s2;
    cudaEvent_t ev_fork, ev_join;
    cudaStreamCreateWithFlags(&s2, cudaStreamNonBlocking);
    cudaEventCreateWithFlags(&ev_fork, cudaEventDisableTiming);
    cudaEventCreateWithFlags(&ev_join, cudaEventDisableTiming);
    cudaEventRecord(ev_fork, 0);
    cudaStreamWaitEvent(s2, ev_fork, 0);

    k_transpose<<<dim3(HDIM / 32, DDIM / 32), dim3(32, 8), 0, s2>>>(Wd1, p_wt1, DDIM, HDIM);
    k_transpose<<<dim3(HDIM / 32, HDIM / 32), dim3(32, 8), 0, s2>>>(Wd2, p_wt2, HDIM, HDIM);
    k_cnorm<<<KCB / 8, 256, 0, s2>>>(cb, p_cn, p_cbh);
    cudaEventRecord(ev_join, s2);

    // ---- main stream: encoder (fp32-exact — argmin-critical) ----
    k_enc1<<<(NTOK * HDIM) / 1024, 256>>>(action, W1, b1, p_h1);
    sgemm<1><<<dim3(HDIM / 128, NTOK / 128), 256>>>(p_h1, W2, b2, p_h2, NTOK, HDIM, HDIM);
    sgemm<0><<<dim3(DDIM / 128, NTOK / 128), 256>>>(p_h2, Wmu, bmu, p_lat, NTOK, DDIM, HDIM);

    // join the prep branch before VQ (screen needs cbh/cn; decoder needs wt1/wt2)
    cudaStreamWaitEvent(0, ev_join, 0);

    // vector quantization: fp16 tensor screening + exact verify (fused norm)
    k_vq_screen<<<NTOK / 64, 256, SCH_SMEM>>>(p_lat, p_cbh, p_cn, p_cand, p_ccnt);
    k_vq_exact<<<VQ2_BLOCKS, 256>>>(p_lat, cb, p_cn, p_cand, p_ccnt,
                                    out, p_qh, p_part);

    // decoder (fp16 tensor-core; h2 fp32 — precision-critical for output 2)
    tc_gemm_f16<1><<<dim3(HDIM / 128, NTOK / 128), 256, TCH_SMEM>>>(p_qh, p_wt1, bd1, p_h1h, HDIM, DDIM);
    tc_gemm_f16<0><<<dim3(HDIM / 128, NTOK / 128), 256, TCH_SMEM>>>(p_h1h, p_wt2, bd2, p_h2, HDIM, HDIM);
    k_dec3<<<NTOK / 8, 256>>>(p_h2, Wd3, bd3, out);

    // scalar loss
    k_loss<<<1, 256>>>(p_part, out);
}

// round 17
// speedup vs baseline: 1.0614x; 1.0494x over previous
#include <cuda_runtime.h>
#include <cuda_fp16.h>
#include <math.h>
#include <stdint.h>

// Problem dims
#define NTOK 32768
#define ADIM 6
#define HDIM 1024
#define DDIM 128
#define KCB  4096

// Output layout (float32, concatenated in reference-return order)
#define OUT_INDS 0
#define OUT_Q    (NTOK)
#define OUT_REC  (NTOK + NTOK * DDIM)
#define OUT_LOSS (NTOK + NTOK * DDIM + NTOK * ADIM)

#define CAPS 64
#define TAU 8e-6f
#define VQ_BLOCKS (NTOK / 64)   // 512

// -------- scratch (device globals; no runtime allocation) --------
__device__ float g_h1[NTOK * HDIM];
__device__ float g_h2[NTOK * HDIM];    // fp32 h2 (precision-critical for out2)
__device__ __half g_h1h[NTOK * HDIM];  // fp16 h1 (decoder intermediate)
__device__ float g_lat[NTOK * DDIM];
__device__ __half g_qh[NTOK * DDIM];   // fp16 quantized_st (decoder input)
__device__ float g_cn[KCB];
__device__ __half g_cbh[KCB * DDIM];   // fp16 codebook (screen only)
__device__ float g_part[VQ_BLOCKS];
__device__ __half g_wt1[HDIM * DDIM];  // Wd1^T fp16
__device__ __half g_wt2[HDIM * HDIM];  // Wd2^T fp16

__device__ __forceinline__ uint32_t smem_u32(const void* p)
{
    uint32_t a;
    asm("{ .reg .u64 t; cvta.to.shared.u64 t, %1; cvt.u32.u64 %0, t; }"
        : "=r"(a) : "l"(p));
    return a;
}
__device__ __forceinline__ void cp16(uint32_t dst, const void* src)
{
    asm volatile("cp.async.cg.shared.global [%0], [%1], 16;"
                 :: "r"(dst), "l"(src) : "memory");
}
__device__ __forceinline__ void mma_f16(float* c, const uint32_t* a, const uint32_t* b)
{
    asm("mma.sync.aligned.m16n8k16.row.col.f32.f16.f16.f32 "
        "{%0,%1,%2,%3}, {%4,%5,%6,%7}, {%8,%9}, {%0,%1,%2,%3};"
        : "+f"(c[0]), "+f"(c[1]), "+f"(c[2]), "+f"(c[3])
        : "r"(a[0]), "r"(a[1]), "r"(a[2]), "r"(a[3]), "r"(b[0]), "r"(b[1]));
}

// ---------------------------------------------------------------------------
// Codebook norms + fp16 codebook (XLA-order reduction, argmin-tie critical)
// ---------------------------------------------------------------------------
__global__ void k_cnorm(const float* __restrict__ cb, float* __restrict__ cn,
                        __half* __restrict__ cbh)
{
    int w = (blockIdx.x * blockDim.x + threadIdx.x) >> 5;
    int lane = threadIdx.x & 31;
    const float* row = cb + w * DDIM;
    __half* hrow = cbh + (size_t)w * DDIM;
    float acc = 0.f;
#pragma unroll
    for (int i = 0; i < 4; i++) {
        float v = row[lane + i * 32];
        hrow[lane + i * 32] = __float2half_rn(v);
        acc = __fadd_rn(acc, __fmul_rn(v, v));
    }
#pragma unroll
    for (int off = 16; off >= 1; off >>= 1)
        acc = __fadd_rn(acc, __shfl_down_sync(0xffffffffu, acc, off));
    if (lane == 0) cn[w] = acc;
}

// ---------------------------------------------------------------------------
// Encoder layer 1 (A=6), 4 outputs/thread (round-11 proven)
// ---------------------------------------------------------------------------
__global__ void k_enc1(const float* __restrict__ act, const float* __restrict__ W1,
                       const float* __restrict__ b1, float* __restrict__ h1)
{
    int gid = blockIdx.x * blockDim.x + threadIdx.x;
    int n = gid >> 8;
    int h = (gid & 255) * 4;
    const float* a = act + n * ADIM;
    float av[ADIM];
#pragma unroll
    for (int k = 0; k < ADIM; k++) av[k] = a[k];
    float4 s = make_float4(0.f, 0.f, 0.f, 0.f);
#pragma unroll
    for (int k = 0; k < ADIM; k++) {
        float4 w = *(const float4*)(W1 + k * HDIM + h);
        s.x = __fmaf_rn(av[k], w.x, s.x);
        s.y = __fmaf_rn(av[k], w.y, s.y);
        s.z = __fmaf_rn(av[k], w.z, s.z);
        s.w = __fmaf_rn(av[k], w.w, s.w);
    }
    float4 b = *(const float4*)(b1 + h);
    s.x = fmaxf(__fadd_rn(s.x, b.x), 0.f);
    s.y = fmaxf(__fadd_rn(s.y, b.y), 0.f);
    s.z = fmaxf(__fadd_rn(s.z, b.z), 0.f);
    s.w = fmaxf(__fadd_rn(s.w, b.w), 0.f);
    *(float4*)(h1 + (size_t)n * HDIM + h) = s;
}

// ---------------------------------------------------------------------------
// FP32 SGEMM (round-3 proven) — ENCODER ONLY (argmin-critical path)
// ---------------------------------------------------------------------------
template <int RELU>
__global__ __launch_bounds__(256)
void sgemm(const float* __restrict__ Am, const float* __restrict__ Bm,
           const float* __restrict__ bias, float* __restrict__ Cm,
           int M, int Nn, int Kk)
{
    __shared__ float As[8][128];
    __shared__ float Bs[8][128];

    int tid = threadIdx.x;
    int tx = tid & 15;
    int ty = tid >> 4;
    int mb = blockIdx.y * 128;
    int nb = blockIdx.x * 128;

    int arow = tid >> 1;
    int acol = (tid & 1) * 4;
    int brow = tid >> 5;
    int bcol = (tid & 31) * 4;

    const float* Aptr = Am + (mb + arow) * Kk + acol;
    const float* Bptr = Bm + brow * Nn + nb + bcol;

    float acc[8][8];
#pragma unroll
    for (int i = 0; i < 8; i++)
#pragma unroll
        for (int j = 0; j < 8; j++) acc[i][j] = 0.f;

    for (int k0 = 0; k0 < Kk; k0 += 8) {
        float4 av = *(const float4*)Aptr;
        As[acol + 0][arow] = av.x;
        As[acol + 1][arow] = av.y;
        As[acol + 2][arow] = av.z;
        As[acol + 3][arow] = av.w;
        *(float4*)&Bs[brow][bcol] = *(const float4*)Bptr;
        __syncthreads();

#pragma unroll
        for (int kk = 0; kk < 8; kk++) {
            float4 a0 = *(const float4*)&As[kk][ty * 8];
            float4 a1 = *(const float4*)&As[kk][ty * 8 + 4];
            float4 b0 = *(const float4*)&Bs[kk][tx * 8];
            float4 b1 = *(const float4*)&Bs[kk][tx * 8 + 4];
            float av8[8] = {a0.x, a0.y, a0.z, a0.w, a1.x, a1.y, a1.z, a1.w};
            float bv8[8] = {b0.x, b0.y, b0.z, b0.w, b1.x, b1.y, b1.z, b1.w};
#pragma unroll
            for (int i = 0; i < 8; i++)
#pragma unroll
                for (int j = 0; j < 8; j++)
                    acc[i][j] = __fmaf_rn(av8[i], bv8[j], acc[i][j]);
        }
        __syncthreads();
        Aptr += 8;
        Bptr += 8 * Nn;
    }

#pragma unroll
    for (int i = 0; i < 8; i++) {
        int row = mb + ty * 8 + i;
        float* Crow = Cm + row * Nn + nb + tx * 8;
        const float* brow2 = bias + nb + tx * 8;
#pragma unroll
        for (int j = 0; j < 8; j++) {
            float v = __fadd_rn(acc[i][j], brow2[j]);
            if (RELU) v = fmaxf(v, 0.f);
            Crow[j] = v;
        }
    }
}

// ===========================================================================
// Fused VQ: fp16 m16n8k16 tensor screening (round-11 proven core) + in-block
// exact verification (k_vq_exact token-for-token: XLA-order row norm, serial
// FFMA candidate dots, lowest-index tie-break, gather/qst/loss epilogue).
// ===========================================================================
#define SCH_ST 68
#define SCH_LAT (64 * SCH_ST)
#define SCH_CB  (32 * SCH_ST)
#define SCH_SMEM ((SCH_LAT + 3 * SCH_CB) * 4)

__global__ __launch_bounds__(256, 2)
void k_vq(const float* __restrict__ lat, const __half* __restrict__ cbh,
          const float* __restrict__ cb, const float* __restrict__ cn,
          float* __restrict__ out, __half* __restrict__ gq,
          float* __restrict__ part)
{
    extern __shared__ uint32_t smh[];
    uint32_t* Lw = smh;
    uint32_t* Cw = smh + SCH_LAT;
    __shared__ unsigned short s_cand[64 * CAPS];
    __shared__ float s_dv[64 * CAPS];
    __shared__ float s_minw[64][2];
    __shared__ int s_cnt[64];
    __shared__ float s_row[8][132];
    __shared__ float s_ps[8];

    int tid = threadIdx.x;
    int lane = tid & 31, warp = tid >> 5;
    int wm = warp & 3, wn = warp >> 2;
    int g = lane >> 2, tg = lane & 3;
    int m0 = blockIdx.x * 64;

    if (tid < 64) s_cnt[tid] = 0;

    {
        int r = tid >> 2;
        int c0w = (tid & 3) * 16;
        const float4* src = (const float4*)(lat + (size_t)(m0 + r) * DDIM + (tid & 3) * 32);
        uint32_t* dst = Lw + r * SCH_ST + c0w;
#pragma unroll
        for (int i = 0; i < 8; i++) {
            float4 v = src[i];
            __half2 h0 = __floats2half2_rn(v.x, v.y);
            __half2 h1 = __floats2half2_rn(v.z, v.w);
            dst[i * 2] = *(uint32_t*)&h0;
            dst[i * 2 + 1] = *(uint32_t*)&h1;
        }
    }

    uint32_t sb = smem_u32(Cw);
    int cr = tid >> 3;
    int ck = tid & 7;

#pragma unroll
    for (int p = 0; p < 2; p++) {
        const __half* src = cbh + (size_t)(p * 32 + cr) * DDIM;
        uint32_t d = sb + (uint32_t)(p * SCH_CB + cr * SCH_ST) * 4;
        cp16(d + ck * 16, src + ck * 8);
        cp16(d + (ck + 8) * 16, src + (ck + 8) * 8);
        asm volatile("cp.async.commit_group;" ::: "memory");
    }

    float rmin0 = 3.4e38f, rmin1 = 3.4e38f;
    int r0 = wm * 16 + g, r1 = r0 + 8;
    const uint32_t* Ar0 = Lw + r0 * SCH_ST;
    const uint32_t* Ar1 = Lw + r1 * SCH_ST;

    for (int ch = 0; ch < 128; ch++) {
        asm volatile("cp.async.wait_group 1;" ::: "memory");
        __syncthreads();

        int p2 = ch + 2;
        if (p2 < 128) {
            int nbuf = p2 - (p2 / 3) * 3;
            const __half* src = cbh + (size_t)(p2 * 32 + cr) * DDIM;
            uint32_t d = sb + (uint32_t)(nbuf * SCH_CB + cr * SCH_ST) * 4;
            cp16(d + ck * 16, src + ck * 8);
            cp16(d + (ck + 8) * 16, src + (ck + 8) * 8);
        }
        asm volatile("cp.async.commit_group;" ::: "memory");

        int buf = ch - (ch / 3) * 3;
        const uint32_t* Cb = Cw + buf * SCH_CB;

        float acc[2][4];
#pragma unroll
        for (int ni = 0; ni < 2; ni++)
#pragma unroll
            for (int q = 0; q < 4; q++) acc[ni][q] = 0.f;

#pragma unroll
        for (int k8 = 0; k8 < 8; k8++) {
            int k0 = k8 * 8;
            uint32_t af[4];
            af[0] = Ar0[k0 + tg];
            af[1] = Ar1[k0 + tg];
            af[2] = Ar0[k0 + tg + 4];
            af[3] = Ar1[k0 + tg + 4];
#pragma unroll
            for (int ni = 0; ni < 2; ni++) {
                const uint32_t* Br = Cb + (wn * 16 + ni * 8 + g) * SCH_ST + k0;
                uint32_t bf[2] = {Br[tg], Br[tg + 4]};
                mma_f16(acc[ni], af, bf);
            }
        }

        float dv[2][4];
        int cbase[2];
        float dmin0 = 3.4e38f, dmin1 = 3.4e38f;
#pragma unroll
        for (int ni = 0; ni < 2; ni++) {
            int code0 = ch * 32 + wn * 16 + ni * 8 + tg * 2;
            float c0v = __ldg(cn + code0);
            float c1v = __ldg(cn + code0 + 1);
            dv[ni][0] = c0v - 2.f * acc[ni][0];
            dv[ni][1] = c1v - 2.f * acc[ni][1];
            dv[ni][2] = c0v - 2.f * acc[ni][2];
            dv[ni][3] = c1v - 2.f * acc[ni][3];
            cbase[ni] = code0;
            dmin0 = fminf(dmin0, fminf(dv[ni][0], dv[ni][1]));
            dmin1 = fminf(dmin1, fminf(dv[ni][2], dv[ni][3]));
        }
        dmin0 = fminf(dmin0, __shfl_xor_sync(0xffffffffu, dmin0, 1));
        dmin0 = fminf(dmin0, __shfl_xor_sync(0xffffffffu, dmin0, 2));
        dmin1 = fminf(dmin1, __shfl_xor_sync(0xffffffffu, dmin1, 1));
        dmin1 = fminf(dmin1, __shfl_xor_sync(0xffffffffu, dmin1, 2));
        rmin0 = fminf(rmin0, dmin0);
        rmin1 = fminf(rmin1, dmin1);
        float th0 = rmin0 + TAU, th1 = rmin1 + TAU;

#pragma unroll
        for (int ni = 0; ni < 2; ni++) {
#pragma unroll
            for (int h = 0; h < 2; h++) {
                float d0 = dv[ni][h];
                if (d0 <= th0) {
                    int s_ = atomicAdd(&s_cnt[r0], 1);
                    if (s_ < CAPS) {
                        s_cand[r0 * CAPS + s_] = (unsigned short)(cbase[ni] + h);
                        s_dv[r0 * CAPS + s_] = d0;
                    }
                }
                float d1 = dv[ni][h + 2];
                if (d1 <= th1) {
                    int s_ = atomicAdd(&s_cnt[r1], 1);
                    if (s_ < CAPS) {
                        s_cand[r1 * CAPS + s_] = (unsigned short)(cbase[ni] + h);
                        s_dv[r1 * CAPS + s_] = d1;
                    }
                }
            }
        }
    }

    // publish per-code-warp final mins
    __syncthreads();
    if (tg == 0) {
        s_minw[r0][wn] = rmin0;
        s_minw[r1][wn] = rmin1;
    }
    __syncthreads();

    // post-filter against FINAL approx min + TAU; compact in place (smem only)
    if (tid < 64) {
        int r = tid;
        int n = s_cnt[r];
        if (n <= CAPS) {
            float th = fminf(s_minw[r][0], s_minw[r][1]) + TAU;
            int k = 0;
            for (int i = 0; i < n; i++) {
                if (s_dv[r * CAPS + i] <= th) {
                    s_cand[r * CAPS + k] = s_cand[r * CAPS + i];
                    k++;
                }
            }
            s_cnt[r] = k;
        }
    }
    __syncthreads();

    // ---- fused exact verification (k_vq_exact semantics, token-for-token) --
    float wsum = 0.f;
    for (int rr = 0; rr < 8; rr++) {
        int rloc = warp * 8 + rr;
        int r = m0 + rloc;

        ((float4*)s_row[warp])[lane] = ((const float4*)(lat + (size_t)r * DDIM))[lane];
        __syncwarp();
        const float* lrow = s_row[warp];

        // XLA-order row norm (bit-identical to proven k_rownorm chain)
        float Lr;
        {
            float nacc = 0.f;
#pragma unroll
            for (int i = 0; i < 4; i++) {
                float v = lrow[lane + i * 32];
                nacc = __fadd_rn(nacc, __fmul_rn(v, v));
            }
#pragma unroll
            for (int off = 16; off >= 1; off >>= 1)
                nacc = __fadd_rn(nacc, __shfl_down_sync(0xffffffffu, nacc, off));
            Lr = __shfl_sync(0xffffffffu, nacc, 0);
        }

        int cnt = s_cnt[rloc];
        float bestv = 3.4e38f;
        int besti = 0x7FFFFFFF;

        if (cnt <= CAPS) {
            if (lane < cnt) {
                int code = s_cand[rloc * CAPS + lane];
                const float4* c4 = (const float4*)(cb + (size_t)code * DDIM);
                float acc = 0.f;
#pragma unroll
                for (int i = 0; i < 32; i++) {
                    float4 c = __ldg(c4 + i);
                    acc = __fmaf_rn(lrow[i * 4 + 0], c.x, acc);
                    acc = __fmaf_rn(lrow[i * 4 + 1], c.y, acc);
                    acc = __fmaf_rn(lrow[i * 4 + 2], c.z, acc);
                    acc = __fmaf_rn(lrow[i * 4 + 3], c.w, acc);
                }
                bestv = __fsub_rn(__fadd_rn(Lr, __ldg(cn + code)),
                                  __fmul_rn(2.f, acc));
                besti = code;
            }
        } else {
            // overflow fallback (expected ~never): full exact scan, vectorized
            for (int c0 = lane; c0 < KCB; c0 += 32) {
                const float4* c4 = (const float4*)(cb + (size_t)c0 * DDIM);
                float acc = 0.f;
#pragma unroll 8
                for (int i = 0; i < 32; i++) {
                    float4 c = __ldg(c4 + i);
                    acc = __fmaf_rn(lrow[i * 4 + 0], c.x, acc);
                    acc = __fmaf_rn(lrow[i * 4 + 1], c.y, acc);
                    acc = __fmaf_rn(lrow[i * 4 + 2], c.z, acc);
                    acc = __fmaf_rn(lrow[i * 4 + 3], c.w, acc);
                }
                float dist = __fsub_rn(__fadd_rn(Lr, __ldg(cn + c0)),
                                       __fmul_rn(2.f, acc));
                if (dist < bestv || (dist == bestv && c0 < besti)) {
                    bestv = dist; besti = c0;
                }
            }
        }

#pragma unroll
        for (int o = 16; o >= 1; o >>= 1) {
            float ov = __shfl_xor_sync(0xffffffffu, bestv, o);
            int oi = __shfl_xor_sync(0xffffffffu, besti, o);
            if (ov < bestv || (ov == bestv && oi < besti)) { bestv = ov; besti = oi; }
        }

        if (lane == 0) out[OUT_INDS + r] = (float)besti;

        const float* qrow = cb + (size_t)besti * DDIM;
#pragma unroll
        for (int i = 0; i < 4; i++) {
            int d = lane + i * 32;
            float l = lrow[d], q = qrow[d];
            float qmL = q - l;
            float qst = l + qmL;
            out[OUT_Q + (size_t)r * DDIM + d] = qst;
            gq[(size_t)r * DDIM + d] = __float2half_rn(qst);
            wsum += qmL * qmL;
        }
        __syncwarp();
    }

#pragma unroll
    for (int o = 16; o >= 1; o >>= 1)
        wsum += __shfl_xor_sync(0xffffffffu, wsum, o);
    if (lane == 0) s_ps[warp] = wsum;
    __syncthreads();
    if (tid == 0) {
        float s = 0.f;
        for (int i = 0; i < 8; i++) s += s_ps[i];
        part[blockIdx.x] = s;
    }
}

// ---------------------------------------------------------------------------
// Weight transpose + fp16 convert: out[c][r] = fp16(in[r][c])
// ---------------------------------------------------------------------------
__global__ void k_transpose(const float* __restrict__ in, __half* __restrict__ out,
                            int R, int C)
{
    __shared__ float t[32][33];
    int c0 = blockIdx.x * 32, r0 = blockIdx.y * 32;
    int x = threadIdx.x, y0 = threadIdx.y;
#pragma unroll
    for (int dy = 0; dy < 32; dy += 8)
        t[y0 + dy][x] = in[(r0 + y0 + dy) * C + c0 + x];
    __syncthreads();
#pragma unroll
    for (int dy = 0; dy < 32; dy += 8)
        out[(c0 + y0 + dy) * R + r0 + x] = __float2half_rn(t[x][y0 + dy]);
}

// ===========================================================================
// tc_gemm_f16 (round-12 proven): fp16 m16n8k16 GEMM, cp.async 3-stage ring.
// OUT16=1 -> fp16 output (chained GEMM), OUT16=0 -> fp32 output.
// ===========================================================================
#define TCH_ST 36
#define TCH_TILE (128 * TCH_ST)
#define TCH_SMEM (3 * 2 * TCH_TILE * 4)

template <int OUT16>
__global__ __launch_bounds__(256, 2)
void tc_gemm_f16(const __half* __restrict__ Am, const __half* __restrict__ Bt,
                 const float* __restrict__ bias, void* __restrict__ Cout,
                 int Nn, int Kk)
{
    extern __shared__ uint32_t smw[];
    uint32_t sbase = smem_u32(smw);

    int tid = threadIdx.x;
    int lane = tid & 31, warp = tid >> 5;
    int wm = warp & 3, wn = warp >> 2;
    int g = lane >> 2, tg = lane & 3;
    int mb = blockIdx.y * 128, nb = blockIdx.x * 128;

    int lr = tid >> 1;
    int lhh = (tid & 1) * 32;
    int lhw = (tid & 1) * 16;

    const __half* Ap = Am + (size_t)(mb + lr) * Kk + lhh;
    const __half* Bp = Bt + (size_t)(nb + lr) * Kk + lhh;
    uint32_t stg_off = (uint32_t)(lr * TCH_ST + lhw) * 4;

    float acc[2][8][4];
#pragma unroll
    for (int mi = 0; mi < 2; mi++)
#pragma unroll
        for (int ni = 0; ni < 8; ni++)
#pragma unroll
            for (int q = 0; q < 4; q++) acc[mi][ni][q] = 0.f;

    int NC = Kk >> 6;

#pragma unroll
    for (int p = 0; p < 2; p++) {
        uint32_t da = sbase + (uint32_t)(p * 2 * TCH_TILE) * 4 + stg_off;
        uint32_t db = da + (uint32_t)TCH_TILE * 4;
        const __half* sa = Ap + p * 64;
        const __half* sb = Bp + p * 64;
#pragma unroll
        for (int i = 0; i < 4; i++) {
            cp16(da + i * 16, sa + i * 8);
            cp16(db + i * 16, sb + i * 8);
        }
        asm volatile("cp.async.commit_group;" ::: "memory");
    }

    for (int s = 0; s < NC; s++) {
        asm volatile("cp.async.wait_group 1;" ::: "memory");
        __syncthreads();

        int p2 = s + 2;
        if (p2 < NC) {
            int nbuf = p2 - (p2 / 3) * 3;
            uint32_t da = sbase + (uint32_t)(nbuf * 2 * TCH_TILE) * 4 + stg_off;
            uint32_t db = da + (uint32_t)TCH_TILE * 4;
            const __half* sa = Ap + p2 * 64;
            const __half* sb = Bp + p2 * 64;
#pragma unroll
            for (int i = 0; i < 4; i++) {
                cp16(da + i * 16, sa + i * 8);
                cp16(db + i * 16, sb + i * 8);
            }
        }
        asm volatile("cp.async.commit_group;" ::: "memory");

        int buf = s - (s / 3) * 3;
        const uint32_t* Ab = smw + buf * 2 * TCH_TILE;
        const uint32_t* Bb = Ab + TCH_TILE;
#pragma unroll
        for (int k16 = 0; k16 < 4; k16++) {
            int k0 = k16 * 8;
            uint32_t af[2][4], bf[8][2];
#pragma unroll
            for (int mi = 0; mi < 2; mi++) {
                int r = wm * 32 + mi * 16 + g;
                af[mi][0] = Ab[r * TCH_ST + k0 + tg];
                af[mi][1] = Ab[(r + 8) * TCH_ST + k0 + tg];
                af[mi][2] = Ab[r * TCH_ST + k0 + tg + 4];
                af[mi][3] = Ab[(r + 8) * TCH_ST + k0 + tg + 4];
            }
#pragma unroll
            for (int ni = 0; ni < 8; ni++) {
                int n = wn * 64 + ni * 8 + g;
                bf[ni][0] = Bb[n * TCH_ST + k0 + tg];
                bf[ni][1] = Bb[n * TCH_ST + k0 + tg + 4];
            }
#pragma unroll
            for (int mi = 0; mi < 2; mi++)
#pragma unroll
                for (int ni = 0; ni < 8; ni++)
                    mma_f16(acc[mi][ni], af[mi], bf[ni]);
        }
    }

#pragma unroll
    for (int mi = 0; mi < 2; mi++) {
        int row = mb + wm * 32 + mi * 16 + g;
#pragma unroll
        for (int ni = 0; ni < 8; ni++) {
            int col = nb + wn * 64 + ni * 8 + tg * 2;
            float b0 = __ldg(bias + col), b1 = __ldg(bias + col + 1);
            float v0 = fmaxf(acc[mi][ni][0] + b0, 0.f);
            float v1 = fmaxf(acc[mi][ni][1] + b1, 0.f);
            float v2 = fmaxf(acc[mi][ni][2] + b0, 0.f);
            float v3 = fmaxf(acc[mi][ni][3] + b1, 0.f);
            if (OUT16) {
                __half* Cm = (__half*)Cout;
                __half2 h01 = __floats2half2_rn(v0, v1);
                __half2 h23 = __floats2half2_rn(v2, v3);
                *(__half2*)(Cm + (size_t)row * Nn + col) = h01;
                *(__half2*)(Cm + (size_t)(row + 8) * Nn + col) = h23;
            } else {
                float* Cm = (float*)Cout;
                *(float2*)(Cm + (size_t)row * Nn + col) = make_float2(v0, v1);
                *(float2*)(Cm + (size_t)(row + 8) * Nn + col) = make_float2(v2, v3);
            }
        }
    }
}

// ---------------------------------------------------------------------------
// Decoder layer 3: recons = tanh(d2 @ Wd3 + bd3). Warp per row; fp32 d2
// (precision-critical), Wd3 staged in smem.
// ---------------------------------------------------------------------------
__global__ void k_dec3(const float* __restrict__ d2, const float* __restrict__ Wd3,
                       const float* __restrict__ bd3, float* __restrict__ out)
{
    __shared__ float ws[HDIM * ADIM];    // 24KB
    int tid = threadIdx.x;
    for (int e = tid; e < HDIM * ADIM; e += 256)
        ws[e] = Wd3[e];
    __syncthreads();

    int warp = (blockIdx.x * 256 + tid) >> 5;
    int lane = tid & 31;
    const float* row = d2 + (size_t)warp * HDIM;
    float a0 = 0.f, a1 = 0.f, a2 = 0.f, a3 = 0.f, a4 = 0.f, a5 = 0.f;
#pragma unroll 4
    for (int k = lane; k < HDIM; k += 32) {
        float v = row[k];
        const float* w = ws + k * ADIM;
        a0 += v * w[0]; a1 += v * w[1]; a2 += v * w[2];
        a3 += v * w[3]; a4 += v * w[4]; a5 += v * w[5];
    }
#pragma unroll
    for (int off = 16; off; off >>= 1) {
        a0 += __shfl_xor_sync(0xffffffffu, a0, off);
        a1 += __shfl_xor_sync(0xffffffffu, a1, off);
        a2 += __shfl_xor_sync(0xffffffffu, a2, off);
        a3 += __shfl_xor_sync(0xffffffffu, a3, off);
        a4 += __shfl_xor_sync(0xffffffffu, a4, off);
        a5 += __shfl_xor_sync(0xffffffffu, a5, off);
    }
    if (lane == 0) {
        float* o = out + OUT_REC + (size_t)warp * ADIM;
        o[0] = tanhf(a0 + bd3[0]);
        o[1] = tanhf(a1 + bd3[1]);
        o[2] = tanhf(a2 + bd3[2]);
        o[3] = tanhf(a3 + bd3[3]);
        o[4] = tanhf(a4 + bd3[4]);
        o[5] = tanhf(a5 + bd3[5]);
    }
}

// ---------------------------------------------------------------------------
// Final loss reduction (512 partials)
// ---------------------------------------------------------------------------
__global__ void k_loss(const float* __restrict__ part, float* __restrict__ out)
{
    __shared__ float s[256];
    int tid = threadIdx.x;
    s[tid] = part[tid] + part[tid + 256];
    __syncthreads();
    for (int st = 128; st > 0; st >>= 1) {
        if (tid < st) s[tid] += s[tid + st];
        __syncthreads();
    }
    if (tid == 0)
        out[OUT_LOSS] = 1.25f * s[0] / (float)(NTOK * DDIM);
}

// ---------------------------------------------------------------------------
extern "C" void kernel_launch(void* const* d_in, const int* in_sizes, int n_in,
                              void* d_out, int out_size)
{
    const float* action = (const float*)d_in[0];
    const float* W1   = (const float*)d_in[1];
    const float* b1   = (const float*)d_in[2];
    const float* W2   = (const float*)d_in[3];
    const float* b2   = (const float*)d_in[4];
    const float* Wmu  = (const float*)d_in[5];
    const float* bmu  = (const float*)d_in[6];
    const float* cb   = (const float*)d_in[7];
    const float* Wd1  = (const float*)d_in[8];
    const float* bd1  = (const float*)d_in[9];
    const float* Wd2  = (const float*)d_in[10];
    const float* bd2  = (const float*)d_in[11];
    const float* Wd3  = (const float*)d_in[12];
    const float* bd3  = (const float*)d_in[13];
    float* out = (float*)d_out;

    float *p_h1, *p_h2, *p_lat, *p_cn, *p_part;
    __half *p_cbh, *p_h1h, *p_qh, *p_wt1, *p_wt2;
    cudaGetSymbolAddress((void**)&p_h1, g_h1);
    cudaGetSymbolAddress((void**)&p_h2, g_h2);
    cudaGetSymbolAddress((void**)&p_h1h, g_h1h);
    cudaGetSymbolAddress((void**)&p_lat, g_lat);
    cudaGetSymbolAddress((void**)&p_qh, g_qh);
    cudaGetSymbolAddress((void**)&p_cn, g_cn);
    cudaGetSymbolAddress((void**)&p_cbh, g_cbh);
    cudaGetSymbolAddress((void**)&p_part, g_part);
    cudaGetSymbolAddress((void**)&p_wt1, g_wt1);
    cudaGetSymbolAddress((void**)&p_wt2, g_wt2);

    cudaFuncSetAttribute(tc_gemm_f16<1>, cudaFuncAttributeMaxDynamicSharedMemorySize,
                         TCH_SMEM);
    cudaFuncSetAttribute(tc_gemm_f16<0>, cudaFuncAttributeMaxDynamicSharedMemorySize,
                         TCH_SMEM);
    cudaFuncSetAttribute(k_vq, cudaFuncAttributeMaxDynamicSharedMemorySize,
                         SCH_SMEM);

    // ---- fork: independent prep kernels on a side stream (graph branch) ----
    cudaStream_t s2;
    cudaEvent_t ev_fork, ev_join;
    cudaStreamCreateWithFlags(&s2, cudaStreamNonBlocking);
    cudaEventCreateWithFlags(&ev_fork, cudaEventDisableTiming);
    cudaEventCreateWithFlags(&ev_join, cudaEventDisableTiming);
    cudaEventRecord(ev_fork, 0);
    cudaStreamWaitEvent(s2, ev_fork, 0);

    k_transpose<<<dim3(HDIM / 32, DDIM / 32), dim3(32, 8), 0, s2>>>(Wd1, p_wt1, DDIM, HDIM);
    k_transpose<<<dim3(HDIM / 32, HDIM / 32), dim3(32, 8), 0, s2>>>(Wd2, p_wt2, HDIM, HDIM);
    k_cnorm<<<KCB / 8, 256, 0, s2>>>(cb, p_cn, p_cbh);
    cudaEventRecord(ev_join, s2);

    // ---- main stream: encoder (fp32-exact — argmin-critical) ----
    k_enc1<<<(NTOK * HDIM) / 1024, 256>>>(action, W1, b1, p_h1);
    sgemm<1><<<dim3(HDIM / 128, NTOK / 128), 256>>>(p_h1, W2, b2, p_h2, NTOK, HDIM, HDIM);
    sgemm<0><<<dim3(DDIM / 128, NTOK / 128), 256>>>(p_h2, Wmu, bmu, p_lat, NTOK, DDIM, HDIM);

    // join the prep branch before VQ (needs cbh/cn; decoder needs wt1/wt2)
    cudaStreamWaitEvent(0, ev_join, 0);

    // fused VQ: fp16 tensor screening + in-block exact verify
    k_vq<<<VQ_BLOCKS, 256, SCH_SMEM>>>(p_lat, p_cbh, cb, p_cn, out, p_qh, p_part);

    // decoder (fp16 tensor-core; h2 fp32 — precision-critical for output 2)
    tc_gemm_f16<1><<<dim3(HDIM / 128, NTOK / 128), 256, TCH_SMEM>>>(p_qh, p_wt1, bd1, p_h1h, HDIM, DDIM);
    tc_gemm_f16<0><<<dim3(HDIM / 128, NTOK / 128), 256, TCH_SMEM>>>(p_h1h, p_wt2, bd2, p_h2, HDIM, HDIM);
    k_dec3<<<NTOK / 8, 256>>>(p_h2, Wd3, bd3, out);

    // scalar loss
    k_loss<<<1, 256>>>(p_part, out);
}